// round 11
// baseline (speedup 1.0000x reference)
#include <cuda_runtime.h>
#include <cuda_fp16.h>
#include <mma.h>
#include <cstdint>

using namespace nvcuda;

// Problem dims
#define BB    64
#define NN    512
#define DIN   256
#define DOUTD 256
#define DOP   64
#define MTOT  (BB*NN)      // 32768

// ---------------- scratch (static device globals) ----------------
__device__ __half g_WH[512 * 256];                    // rows 0-255: M^T (Q/K folded) | 256-511: dgf_W^T
__device__ __half g_Wcombh[512 * 256];                // rows 0-255: Wv | 256-511: dgf_W^T
__device__ __half g_Woph[512 * 64];                   // rows 0-255: dgf_opW | 256-511: gat_opW
__device__ float  g_biascat[512];
__device__ __half g_Xh[(size_t)MTOT * DIN];           // half inputs
__device__ __half g_OPh[(size_t)MTOT * DOP];          // half op_emb
__device__ __half g_Yh[(size_t)MTOT * 256];           // Y = X @ M (half)
__device__ float  g_SUP[(size_t)MTOT * 256];          // support (exact fp32)
__device__ float  g_G[(size_t)MTOT * 512];            // gate pre-acts
__device__ __half g_VSh[(size_t)BB * 512 * 512];      // per batch: rows 0-255 Whv^T | 256-511 support^T
__device__ float  g_S[(size_t)BB * NN * NN];          // scores (fp32)
__device__ __half g_attnh[(size_t)BB * NN * NN];      // softmax(attn) half
__device__ __half g_adjh[(size_t)BB * NN * NN];       // adj half
__device__ float  g_AV[(size_t)MTOT * 256];
__device__ float  g_AS[(size_t)MTOT * 256];

// ---------------- PTX helpers ----------------
__device__ __forceinline__ uint32_t smem_u32(const void* p) {
    uint32_t a;
    asm("{ .reg .u64 t; cvta.to.shared.u64 t, %1; cvt.u32.u64 %0, t; }" : "=r"(a) : "l"(p));
    return a;
}
__device__ __forceinline__ void cp16s(uint32_t dst, const void* src) {
    asm volatile("cp.async.cg.shared.global [%0], [%1], 16;" :: "r"(dst), "l"(src));
}

// ---------------- M^T precompute: g_WH[j,i] = sum_m Wq[m,i]*a_w[m]/16*Wk[m,j] ----------------
__global__ void mt_kernel(const float* __restrict__ Wq, const float* __restrict__ Wk,
                          const float* __restrict__ a_w)
{
    __shared__ float wk[256];
    const int j = blockIdx.x, i = threadIdx.x;
    wk[i] = Wk[i * 256 + j] * a_w[i] * 0.0625f;
    __syncthreads();
    float s = 0.0f;
#pragma unroll 8
    for (int m = 0; m < 256; m++) s += Wq[m * 256 + i] * wk[m];
    g_WH[j * 256 + i] = __float2half_rn(s);
}

// ---------------- prep: pack weights as half ----------------
__global__ void prep_kernel(const float* __restrict__ dgf_W,
                            const float* __restrict__ Wv,
                            const float* __restrict__ dgf_opW,
                            const float* __restrict__ gat_opW,
                            const float* __restrict__ dgf_opb,
                            const float* __restrict__ gat_opb)
{
    int idx = blockIdx.x * blockDim.x + threadIdx.x;
    if (idx < 256 * 256) {   // g_WH rows 256-511 = dgf_W^T
        int o = idx >> 8, i = idx & 255;
        g_WH[(256 + o) * 256 + i] = __float2half_rn(dgf_W[i * 256 + o]);
    }
    if (idx < 512 * 256) {   // g_Wcombh
        int m = idx >> 8, i = idx & 255;
        float v = (m < 256) ? Wv[m * 256 + i] : dgf_W[i * 256 + (m - 256)];
        g_Wcombh[idx] = __float2half_rn(v);
    }
    if (idx < 512 * 64) {
        int n = idx >> 6, p = idx & 63;
        float v = (n < 256) ? dgf_opW[n * 64 + p] : gat_opW[(n - 256) * 64 + p];
        g_Woph[idx] = __float2half_rn(v);
    }
    if (idx < 512) {
        g_biascat[idx] = (idx < 256) ? dgf_opb[idx] : gat_opb[idx - 256];
    }
}

// ---------------- float -> half copy ----------------
__global__ void f2h_copy(const float4* __restrict__ src, __half2* __restrict__ dst, int n4)
{
    int i = blockIdx.x * blockDim.x + threadIdx.x;
    if (i < n4) {
        float4 v = src[i];
        dst[2 * i]     = __floats2half2_rn(v.x, v.y);
        dst[2 * i + 1] = __floats2half2_rn(v.z, v.w);
    }
}

// ---------------- fp16 wmma GEMM: C[M,N] = A[M,K] @ B[N,K]^T ----------------
// 128x256 CTA tile, 8 warps (2x4), 64x64 warp tile, BK=64, 3-stage cp.async pipeline.
// mode 0: fp32 out to Cf. mode 1: half out to Ch. mode 2: bn<256 -> half Ch @col bn, else fp32 Cf @col bn-256.
constexpr int BM  = 128;
constexpr int BN  = 256;
constexpr int BKH = 64;
constexpr int LDH = 72;                     // halfs per smem row (144B stride)
constexpr int ASTG = BM * LDH;              // 9216 halfs
constexpr int BSTG = BN * LDH;              // 18432 halfs
constexpr int STG1 = ASTG + BSTG;           // halfs per stage (27648 = 55296 B)

__global__ __launch_bounds__(256, 1)
void gemm_h(const __half* __restrict__ A, const __half* __restrict__ B,
            float* __restrict__ Cf, __half* __restrict__ Ch,
            int lda, int ldb, int ldcf, int ldch, int T, int mode,
            size_t sA, size_t sB, size_t sCf, size_t sCh)
{
    extern __shared__ __half smraw[];
    __half* sm = (__half*)(((uintptr_t)smraw + 127) & ~(uintptr_t)127);

    A += (size_t)blockIdx.z * sA;
    B += (size_t)blockIdx.z * sB;
    Cf += (size_t)blockIdx.z * sCf;
    Ch += (size_t)blockIdx.z * sCh;

    const int bm = blockIdx.y * BM, bn = blockIdx.x * BN;
    const int tid = threadIdx.x, warp = tid >> 5;
    const int wm = (warp >> 2) * 64;        // 2 warp rows
    const int wn = (warp & 3) * 64;         // 4 warp cols

    wmma::fragment<wmma::accumulator, 16, 16, 16, float> acc[4][4];
#pragma unroll
    for (int i = 0; i < 4; i++)
#pragma unroll
        for (int j = 0; j < 4; j++) wmma::fill_fragment(acc[i][j], 0.0f);

    auto load_stage = [&](int s, int t) {
        __half* as = sm + (size_t)s * STG1;
        __half* bs = as + ASTG;
        const int k0 = t * BKH;
#pragma unroll
        for (int it = 0; it < 4; it++) {     // A: 128x64 = 1024 cp16
            int idx = tid + it * 256;
            int rr = idx >> 3, cc = idx & 7;
            cp16s(smem_u32(as + rr * LDH + cc * 8),
                  A + (size_t)(bm + rr) * lda + k0 + cc * 8);
        }
#pragma unroll
        for (int it = 0; it < 8; it++) {     // B: 256x64 = 2048 cp16
            int idx = tid + it * 256;
            int rr = idx >> 3, cc = idx & 7;
            cp16s(smem_u32(bs + rr * LDH + cc * 8),
                  B + (size_t)(bn + rr) * ldb + k0 + cc * 8);
        }
        asm volatile("cp.async.commit_group;");
    };

    // prologue: prefetch 2 stages
    load_stage(0, 0);
    if (T > 1) load_stage(1, 1);

    for (int t = 0; t < T; t++) {
        const int s = t % 3;
        if (t + 2 < T) {
            load_stage((t + 2) % 3, t + 2);
            asm volatile("cp.async.wait_group 2;");
        } else if (t + 1 < T) {
            asm volatile("cp.async.wait_group 1;");
        } else {
            asm volatile("cp.async.wait_group 0;");
        }
        __syncthreads();

        const __half* as = sm + (size_t)s * STG1;
        const __half* bs = as + ASTG;
#pragma unroll
        for (int kk = 0; kk < BKH; kk += 16) {
            wmma::fragment<wmma::matrix_a, 16, 16, 16, __half, wmma::row_major> af[4];
#pragma unroll
            for (int ii = 0; ii < 4; ii++)
                wmma::load_matrix_sync(af[ii], as + (wm + 16 * ii) * LDH + kk, LDH);
            wmma::fragment<wmma::matrix_b, 16, 16, 16, __half, wmma::col_major> bf[4];
#pragma unroll
            for (int j = 0; j < 4; j++)
                wmma::load_matrix_sync(bf[j], bs + (wn + 16 * j) * LDH + kk, LDH);
#pragma unroll
            for (int ii = 0; ii < 4; ii++)
#pragma unroll
                for (int j = 0; j < 4; j++)
                    wmma::mma_sync(acc[ii][j], af[ii], bf[j], acc[ii][j]);
        }
        __syncthreads();
    }

    // epilogue
    const bool half_out = (mode == 1) || (mode == 2 && bn < 256);
#pragma unroll
    for (int ii = 0; ii < 4; ii++)
#pragma unroll
        for (int j = 0; j < 4; j++) {
            const int row = bm + wm + 16 * ii;
            const int col = bn + wn + 16 * j;
            if (half_out) {
                wmma::fragment<wmma::accumulator, 16, 16, 16, __half> hf;
#pragma unroll
                for (int t = 0; t < hf.num_elements; t++)
                    hf.x[t] = __float2half_rn(acc[ii][j].x[t]);
                wmma::store_matrix_sync(Ch + (size_t)row * ldch + col, hf, ldch,
                                        wmma::mem_row_major);
            } else {
                const int cf = (mode == 2) ? (col - 256) : col;
                wmma::store_matrix_sync(Cf + (size_t)row * ldcf + cf, acc[ii][j], ldcf,
                                        wmma::mem_row_major);
            }
        }
}

// ---------------- reductions ----------------
__device__ __forceinline__ float warp_max(float v) {
#pragma unroll
    for (int o = 16; o; o >>= 1) v = fmaxf(v, __shfl_xor_sync(0xffffffffu, v, o));
    return v;
}
__device__ __forceinline__ float warp_sum(float v) {
#pragma unroll
    for (int o = 16; o; o >>= 1) v += __shfl_xor_sync(0xffffffffu, v, o);
    return v;
}
__device__ __forceinline__ float block_max_256(float v, float* sh) {
    float w = warp_max(v);
    __syncthreads();
    if ((threadIdx.x & 31) == 0) sh[threadIdx.x >> 5] = w;
    __syncthreads();
    float t = sh[0];
#pragma unroll
    for (int i = 1; i < 8; i++) t = fmaxf(t, sh[i]);
    return t;
}
__device__ __forceinline__ float block_sum_256(float v, float* sh) {
    float w = warp_sum(v);
    __syncthreads();
    if ((threadIdx.x & 31) == 0) sh[threadIdx.x >> 5] = w;
    __syncthreads();
    float t = 0.0f;
#pragma unroll
    for (int i = 0; i < 8; i++) t += sh[i];
    return t;
}

// ------- leaky+mask+softmax over rows of S -> attn (half); also emit adj (half) -------
__global__ void softmax_kernel(const float* __restrict__ adj)
{
    __shared__ float sh[8];
    const int r = blockIdx.x;
    const float* Srow = g_S + (size_t)r * NN;
    const float* arow = adj + (size_t)r * NN;
    __half* Orow = g_attnh + (size_t)r * NN;
    __half* Arow = g_adjh + (size_t)r * NN;
    const int t = threadIdx.x;

    float v0 = Srow[t], v1 = Srow[t + 256];
    float a0 = arow[t], a1 = arow[t + 256];
    Arow[t]       = __float2half_rn(a0);
    Arow[t + 256] = __float2half_rn(a1);
    v0 = (v0 >= 0.0f ? v0 : 0.2f * v0) * a0;
    v1 = (v1 >= 0.0f ? v1 : 0.2f * v1) * a1;

    float m = block_max_256(fmaxf(v0, v1), sh);
    float e0 = expf(v0 - m), e1 = expf(v1 - m);
    float s = block_sum_256(e0 + e1, sh);
    float inv = 1.0f / s;
    Orow[t]       = __float2half_rn(e0 * inv);
    Orow[t + 256] = __float2half_rn(e1 * inv);
}

// ---------------- final: gates + dense residual + LN + blend ----------------
__global__ void final_kernel(const float* __restrict__ dgf_b,
                             const float* __restrict__ ln_g,
                             const float* __restrict__ ln_b,
                             float* __restrict__ out)
{
    __shared__ float sh[8];
    const size_t r = blockIdx.x;
    const int o = threadIdx.x;

    float sup = g_SUP[r * 256 + o];
    float as  = g_AS[r * 256 + o];
    float av  = g_AV[r * 256 + o];
    float gd  = 1.0f / (1.0f + expf(-(g_G[r * 512 + o] + g_biascat[o])));
    float gg  = 1.0f / (1.0f + expf(-(g_G[r * 512 + 256 + o] + g_biascat[256 + o])));

    float dense = gd * as + sup + dgf_b[o];
    float h = gg * av;

    float mean = block_sum_256(h, sh) * (1.0f / 256.0f);
    float d = h - mean;
    float var = block_sum_256(d * d, sh) * (1.0f / 256.0f);
    float gat = d * rsqrtf(var + 1e-5f) * ln_g[o] + ln_b[o];

    out[r * 256 + o] = 0.5f * (dense + gat);
}

// ---------------- launch ----------------
extern "C" void kernel_launch(void* const* d_in, const int* in_sizes, int n_in,
                              void* d_out, int out_size)
{
    const float* inputs  = (const float*)d_in[0];
    const float* adj     = (const float*)d_in[1];
    const float* op_emb  = (const float*)d_in[2];
    const float* dgf_W   = (const float*)d_in[3];
    const float* dgf_b   = (const float*)d_in[4];
    const float* dgf_opW = (const float*)d_in[5];
    const float* dgf_opb = (const float*)d_in[6];
    const float* Wk      = (const float*)d_in[7];
    const float* Wv      = (const float*)d_in[8];
    const float* Wq      = (const float*)d_in[9];
    const float* a_w     = (const float*)d_in[10];
    const float* gat_opW = (const float*)d_in[11];
    const float* gat_opb = (const float*)d_in[12];
    const float* ln_g    = (const float*)d_in[13];
    const float* ln_b    = (const float*)d_in[14];
    float* out = (float*)d_out;

    __half *WH, *Wcombh, *Woph, *Xh, *OPh, *Yh, *VSh, *ATTh, *ADJh;
    float *SUP, *G, *S, *AV, *AS;
    cudaGetSymbolAddress((void**)&WH,     g_WH);
    cudaGetSymbolAddress((void**)&Wcombh, g_Wcombh);
    cudaGetSymbolAddress((void**)&Woph,   g_Woph);
    cudaGetSymbolAddress((void**)&Xh,     g_Xh);
    cudaGetSymbolAddress((void**)&OPh,    g_OPh);
    cudaGetSymbolAddress((void**)&Yh,     g_Yh);
    cudaGetSymbolAddress((void**)&VSh,    g_VSh);
    cudaGetSymbolAddress((void**)&ATTh,   g_attnh);
    cudaGetSymbolAddress((void**)&ADJh,   g_adjh);
    cudaGetSymbolAddress((void**)&SUP,    g_SUP);
    cudaGetSymbolAddress((void**)&G,      g_G);
    cudaGetSymbolAddress((void**)&S,      g_S);
    cudaGetSymbolAddress((void**)&AV,     g_AV);
    cudaGetSymbolAddress((void**)&AS,     g_AS);

    const int DSMEM = 3 * STG1 * (int)sizeof(__half) + 256;   // 3 stages + align pad = ~166KB
    cudaFuncSetAttribute(gemm_h, cudaFuncAttributeMaxDynamicSharedMemorySize, DSMEM);

    // weight prep
    mt_kernel<<<256, 256>>>(Wq, Wk, a_w);
    prep_kernel<<<512, 256>>>(dgf_W, Wv, dgf_opW, gat_opW, dgf_opb, gat_opb);
    // half copies of activations
    f2h_copy<<<(MTOT * DIN / 4 + 255) / 256, 256>>>((const float4*)inputs, (__half2*)Xh, MTOT * DIN / 4);
    f2h_copy<<<(MTOT * DOP / 4 + 255) / 256, 256>>>((const float4*)op_emb, (__half2*)OPh, MTOT * DOP / 4);

    // H: X @ [M | dgf_W]^T -> Y (half, cols 0-255) + support (fp32, cols 256-511)
    {
        dim3 grid(2, MTOT / 128, 1);
        gemm_h<<<grid, 256, DSMEM>>>(Xh, WH, SUP, Yh, 256, 256, 256, 256, 4, 2, 0, 0, 0, 0);
    }
    // gates: OPh @ Woph^T -> G fp32 [32768,512]
    {
        dim3 grid(2, MTOT / 128, 1);
        gemm_h<<<grid, 256, DSMEM>>>(OPh, Woph, G, Yh, 64, 64, 512, 0, 1, 0, 0, 0, 0, 0);
    }
    // VS[b] = Wcomb @ X[b]^T -> half [512,512] (rows 0-255 Whv^T, 256-511 support^T)
    {
        dim3 grid(2, 4, BB);
        gemm_h<<<grid, 256, DSMEM>>>(Wcombh, Xh, S, VSh, 256, 256, 0, 512, 4, 1,
                                     0, (size_t)512 * 256, 0, (size_t)512 * 512);
    }
    // scores: S[b] = Y[b] @ X[b]^T -> fp32
    {
        dim3 grid(2, 4, BB);
        gemm_h<<<grid, 256, DSMEM>>>(Yh, Xh, S, Yh, 256, 256, 512, 0, 4, 0,
                                     (size_t)512 * 256, (size_t)512 * 256, (size_t)512 * 512, 0);
    }
    // leaky + mask + softmax -> attn half; adj -> half
    softmax_kernel<<<MTOT, 256>>>(adj);

    // AV[b] = attn[b] @ (Whv^T)^T -> fp32 [512,256]
    {
        dim3 grid(1, 4, BB);
        gemm_h<<<grid, 256, DSMEM>>>(ATTh, VSh, AV, Yh, 512, 512, 256, 0, 8, 0,
                                     (size_t)512 * 512, (size_t)512 * 512, (size_t)512 * 256, 0);
    }
    // AS[b] = adj[b] @ (support^T)^T -> fp32 [512,256]
    {
        dim3 grid(1, 4, BB);
        gemm_h<<<grid, 256, DSMEM>>>(ADJh, VSh + (size_t)256 * 512, AS, Yh, 512, 512, 256, 0, 8, 0,
                                     (size_t)512 * 512, (size_t)512 * 512, (size_t)512 * 256, 0);
    }
    // gates + residual + LN + blend
    final_kernel<<<MTOT, 256>>>(dgf_b, ln_g, ln_b, out);

    (void)in_sizes; (void)n_in; (void)out_size;
}

// round 12
// speedup vs baseline: 1.0717x; 1.0717x over previous
#include <cuda_runtime.h>
#include <cuda_fp16.h>
#include <mma.h>
#include <cstdint>

using namespace nvcuda;

// Problem dims
#define BB    64
#define NN    512
#define DIN   256
#define DOUTD 256
#define DOP   64
#define MTOT  (BB*NN)      // 32768

// ---------------- scratch (static device globals) ----------------
__device__ __half g_W3[768 * 256];                    // rows 0-255: M^T | 256-511: dgf_W^T | 512-767: Wv
__device__ __half g_Woph[512 * 64];                   // rows 0-255: dgf_opW | 256-511: gat_opW
__device__ float  g_biascat[512];
__device__ __half g_Xh[(size_t)MTOT * DIN];           // half inputs
__device__ __half g_OPh[(size_t)MTOT * DOP];          // half op_emb
__device__ __half g_Yh[(size_t)MTOT * 256];           // Y = X @ M (half)
__device__ float  g_SUP[(size_t)MTOT * 256];          // support (exact fp32)
__device__ __half g_SUPh[(size_t)MTOT * 256];         // support (half, for AS GEMM)
__device__ __half g_WhvH[(size_t)MTOT * 256];         // Whv (half, row-major, for AV GEMM)
__device__ __half g_Gh[(size_t)MTOT * 512];           // gate pre-acts (half)
__device__ float  g_S[(size_t)BB * NN * NN];          // scores (fp32)
__device__ __half g_attnh[(size_t)BB * NN * NN];      // softmax(attn) half
__device__ __half g_adjh[(size_t)BB * NN * NN];       // adj half
__device__ float  g_AV[(size_t)MTOT * 256];
__device__ float  g_AS[(size_t)MTOT * 256];

// ---------------- PTX helpers ----------------
__device__ __forceinline__ uint32_t smem_u32(const void* p) {
    uint32_t a;
    asm("{ .reg .u64 t; cvta.to.shared.u64 t, %1; cvt.u32.u64 %0, t; }" : "=r"(a) : "l"(p));
    return a;
}
__device__ __forceinline__ void cp16s(uint32_t dst, const void* src) {
    asm volatile("cp.async.cg.shared.global [%0], [%1], 16;" :: "r"(dst), "l"(src));
}

// ---------------- M^T precompute: g_W3[j,i] = sum_m Wq[m,i]*a_w[m]/16*Wk[m,j] ----------------
__global__ void mt_kernel(const float* __restrict__ Wq, const float* __restrict__ Wk,
                          const float* __restrict__ a_w)
{
    __shared__ float wk[256];
    const int j = blockIdx.x, i = threadIdx.x;
    wk[i] = Wk[i * 256 + j] * a_w[i] * 0.0625f;
    __syncthreads();
    float s = 0.0f;
#pragma unroll 8
    for (int m = 0; m < 256; m++) s += Wq[m * 256 + i] * wk[m];
    g_W3[j * 256 + i] = __float2half_rn(s);
}

// ---------------- prep: pack weights as half ----------------
__global__ void prep_kernel(const float* __restrict__ dgf_W,
                            const float* __restrict__ Wv,
                            const float* __restrict__ dgf_opW,
                            const float* __restrict__ gat_opW,
                            const float* __restrict__ dgf_opb,
                            const float* __restrict__ gat_opb)
{
    int idx = blockIdx.x * blockDim.x + threadIdx.x;
    if (idx < 512 * 256) {   // g_W3 rows 256-767
        int r = idx >> 8, i = idx & 255;
        float v = (r < 256) ? dgf_W[i * 256 + r]            // rows 256-511: dgf_W^T
                            : Wv[(r - 256) * 256 + i];      // rows 512-767: Wv
        g_W3[(256 + r) * 256 + i] = __float2half_rn(v);
    }
    if (idx < 512 * 64) {
        int n = idx >> 6, p = idx & 63;
        float v = (n < 256) ? dgf_opW[n * 64 + p] : gat_opW[(n - 256) * 64 + p];
        g_Woph[idx] = __float2half_rn(v);
    }
    if (idx < 512) {
        g_biascat[idx] = (idx < 256) ? dgf_opb[idx] : gat_opb[idx - 256];
    }
}

// ---------------- float -> half copy ----------------
__global__ void f2h_copy(const float4* __restrict__ src, __half2* __restrict__ dst, int n4)
{
    int i = blockIdx.x * blockDim.x + threadIdx.x;
    if (i < n4) {
        float4 v = src[i];
        dst[2 * i]     = __floats2half2_rn(v.x, v.y);
        dst[2 * i + 1] = __floats2half2_rn(v.z, v.w);
    }
}

// ---------------- fp16 wmma GEMM (R10 config: 128x128 CTA, 32x64 warp, 2-stage) ----------------
// BROW=0: C = A @ B^T, B row-major [N,K] (K contiguous)
// BROW=1: C = A @ B,   B row-major [K,N] (N contiguous)
// mode 0: fp32 -> Cf. mode 1: half -> Ch.
// mode 3 (H kernel, N=768): col<256 -> Ch(Yh); col<512 -> Cf(SUP,fp32)+Ch2(SUPh,half); else -> Ch3(WhvH,half)
constexpr int BKH = 64;
constexpr int LDH = 72;                    // A / BROW0-B smem stride (halfs)
constexpr int LDB_R = 136;                 // BROW1-B smem stride (halfs)
constexpr int ASTG = 128 * LDH;            // 9216 halfs
constexpr int BSTG = 9216;                 // B stage region (BROW0:128*72=9216, BROW1:64*136=8704)
constexpr int STG1 = ASTG + BSTG;          // halfs per stage

template <int BROW>
__global__ __launch_bounds__(256, 2)
void gemm_h(const __half* __restrict__ A, const __half* __restrict__ B,
            float* __restrict__ Cf, __half* __restrict__ Ch,
            __half* __restrict__ Ch2, __half* __restrict__ Ch3,
            int lda, int ldb, int ldcf, int ldch, int T, int mode,
            size_t sA, size_t sB, size_t sCf, size_t sCh)
{
    extern __shared__ __half smraw[];
    __half* sm = (__half*)(((uintptr_t)smraw + 127) & ~(uintptr_t)127);

    A += (size_t)blockIdx.z * sA;
    B += (size_t)blockIdx.z * sB;
    Cf += (size_t)blockIdx.z * sCf;
    Ch += (size_t)blockIdx.z * sCh;

    const int bm = blockIdx.y * 128, bn = blockIdx.x * 128;
    const int tid = threadIdx.x, warp = tid >> 5;
    const int wm = (warp >> 1) * 32;       // 4 warp rows x 32
    const int wn = (warp & 1) * 64;        // 2 warp cols x 64

    wmma::fragment<wmma::accumulator, 16, 16, 16, float> acc[2][4];
#pragma unroll
    for (int i = 0; i < 2; i++)
#pragma unroll
        for (int j = 0; j < 4; j++) wmma::fill_fragment(acc[i][j], 0.0f);

    auto load_stage = [&](int s, int t) {
        __half* as = sm + (size_t)s * STG1;
        __half* bs = as + ASTG;
        const int k0 = t * BKH;
#pragma unroll
        for (int it = 0; it < 4; it++) {     // A: 128 rows x 64 halfs
            int idx = tid + it * 256;
            int rr = idx >> 3, cc = idx & 7;
            cp16s(smem_u32(as + rr * LDH + cc * 8),
                  A + (size_t)(bm + rr) * lda + k0 + cc * 8);
        }
        if (BROW == 0) {
#pragma unroll
            for (int it = 0; it < 4; it++) { // B: 128 N-rows x 64 halfs (K contig)
                int idx = tid + it * 256;
                int rr = idx >> 3, cc = idx & 7;
                cp16s(smem_u32(bs + rr * LDH + cc * 8),
                      B + (size_t)(bn + rr) * ldb + k0 + cc * 8);
            }
        } else {
#pragma unroll
            for (int it = 0; it < 4; it++) { // B: 64 K-rows x 128 halfs (N contig)
                int idx = tid + it * 256;
                int rr = idx >> 4, cc = idx & 15;
                cp16s(smem_u32(bs + rr * LDB_R + cc * 8),
                      B + (size_t)(k0 + rr) * ldb + bn + cc * 8);
            }
        }
        asm volatile("cp.async.commit_group;");
    };

    load_stage(0, 0);

    for (int t = 0; t < T; t++) {
        const int s = t & 1;
        if (t + 1 < T) {
            load_stage(s ^ 1, t + 1);
            asm volatile("cp.async.wait_group 1;");
        } else {
            asm volatile("cp.async.wait_group 0;");
        }
        __syncthreads();

        const __half* as = sm + (size_t)s * STG1;
        const __half* bs = as + ASTG;
#pragma unroll
        for (int kk = 0; kk < BKH; kk += 16) {
            wmma::fragment<wmma::matrix_a, 16, 16, 16, __half, wmma::row_major> af[2];
#pragma unroll
            for (int ii = 0; ii < 2; ii++)
                wmma::load_matrix_sync(af[ii], as + (wm + 16 * ii) * LDH + kk, LDH);
            if (BROW == 0) {
                wmma::fragment<wmma::matrix_b, 16, 16, 16, __half, wmma::col_major> bf[4];
#pragma unroll
                for (int j = 0; j < 4; j++)
                    wmma::load_matrix_sync(bf[j], bs + (wn + 16 * j) * LDH + kk, LDH);
#pragma unroll
                for (int ii = 0; ii < 2; ii++)
#pragma unroll
                    for (int j = 0; j < 4; j++)
                        wmma::mma_sync(acc[ii][j], af[ii], bf[j], acc[ii][j]);
            } else {
                wmma::fragment<wmma::matrix_b, 16, 16, 16, __half, wmma::row_major> bf[4];
#pragma unroll
                for (int j = 0; j < 4; j++)
                    wmma::load_matrix_sync(bf[j], bs + kk * LDB_R + wn + 16 * j, LDB_R);
#pragma unroll
                for (int ii = 0; ii < 2; ii++)
#pragma unroll
                    for (int j = 0; j < 4; j++)
                        wmma::mma_sync(acc[ii][j], af[ii], bf[j], acc[ii][j]);
            }
        }
        __syncthreads();
    }

    // ---- epilogue ----
#pragma unroll
    for (int ii = 0; ii < 2; ii++)
#pragma unroll
        for (int j = 0; j < 4; j++) {
            const int row = bm + wm + 16 * ii;
            const int col = bn + wn + 16 * j;
            if (mode == 0) {
                wmma::store_matrix_sync(Cf + (size_t)row * ldcf + col, acc[ii][j], ldcf,
                                        wmma::mem_row_major);
            } else if (mode == 1) {
                wmma::fragment<wmma::accumulator, 16, 16, 16, __half> hf;
#pragma unroll
                for (int t = 0; t < hf.num_elements; t++)
                    hf.x[t] = __float2half_rn(acc[ii][j].x[t]);
                wmma::store_matrix_sync(Ch + (size_t)row * ldch + col, hf, ldch,
                                        wmma::mem_row_major);
            } else {  // mode 3: H triple output
                if (col < 256) {
                    wmma::fragment<wmma::accumulator, 16, 16, 16, __half> hf;
#pragma unroll
                    for (int t = 0; t < hf.num_elements; t++)
                        hf.x[t] = __float2half_rn(acc[ii][j].x[t]);
                    wmma::store_matrix_sync(Ch + (size_t)row * 256 + col, hf, 256,
                                            wmma::mem_row_major);
                } else if (col < 512) {
                    wmma::store_matrix_sync(Cf + (size_t)row * 256 + (col - 256), acc[ii][j], 256,
                                            wmma::mem_row_major);
                    wmma::fragment<wmma::accumulator, 16, 16, 16, __half> hf;
#pragma unroll
                    for (int t = 0; t < hf.num_elements; t++)
                        hf.x[t] = __float2half_rn(acc[ii][j].x[t]);
                    wmma::store_matrix_sync(Ch2 + (size_t)row * 256 + (col - 256), hf, 256,
                                            wmma::mem_row_major);
                } else {
                    wmma::fragment<wmma::accumulator, 16, 16, 16, __half> hf;
#pragma unroll
                    for (int t = 0; t < hf.num_elements; t++)
                        hf.x[t] = __float2half_rn(acc[ii][j].x[t]);
                    wmma::store_matrix_sync(Ch3 + (size_t)row * 256 + (col - 512), hf, 256,
                                            wmma::mem_row_major);
                }
            }
        }
}

// ---------------- reductions ----------------
__device__ __forceinline__ float warp_max(float v) {
#pragma unroll
    for (int o = 16; o; o >>= 1) v = fmaxf(v, __shfl_xor_sync(0xffffffffu, v, o));
    return v;
}
__device__ __forceinline__ float warp_sum(float v) {
#pragma unroll
    for (int o = 16; o; o >>= 1) v += __shfl_xor_sync(0xffffffffu, v, o);
    return v;
}
__device__ __forceinline__ float block_max_256(float v, float* sh) {
    float w = warp_max(v);
    __syncthreads();
    if ((threadIdx.x & 31) == 0) sh[threadIdx.x >> 5] = w;
    __syncthreads();
    float t = sh[0];
#pragma unroll
    for (int i = 1; i < 8; i++) t = fmaxf(t, sh[i]);
    return t;
}
__device__ __forceinline__ float block_sum_256(float v, float* sh) {
    float w = warp_sum(v);
    __syncthreads();
    if ((threadIdx.x & 31) == 0) sh[threadIdx.x >> 5] = w;
    __syncthreads();
    float t = 0.0f;
#pragma unroll
    for (int i = 0; i < 8; i++) t += sh[i];
    return t;
}

// ------- leaky+mask+softmax over rows of S -> attn (half); also emit adj (half) -------
__global__ void softmax_kernel(const float* __restrict__ adj)
{
    __shared__ float sh[8];
    const int r = blockIdx.x;
    const float* Srow = g_S + (size_t)r * NN;
    const float* arow = adj + (size_t)r * NN;
    __half* Orow = g_attnh + (size_t)r * NN;
    __half* Arow = g_adjh + (size_t)r * NN;
    const int t = threadIdx.x;

    float v0 = Srow[t], v1 = Srow[t + 256];
    float a0 = arow[t], a1 = arow[t + 256];
    Arow[t]       = __float2half_rn(a0);
    Arow[t + 256] = __float2half_rn(a1);
    v0 = (v0 >= 0.0f ? v0 : 0.2f * v0) * a0;
    v1 = (v1 >= 0.0f ? v1 : 0.2f * v1) * a1;

    float m = block_max_256(fmaxf(v0, v1), sh);
    float e0 = expf(v0 - m), e1 = expf(v1 - m);
    float s = block_sum_256(e0 + e1, sh);
    float inv = 1.0f / s;
    Orow[t]       = __float2half_rn(e0 * inv);
    Orow[t + 256] = __float2half_rn(e1 * inv);
}

// ---------------- final: gates + dense residual + LN + blend ----------------
__global__ void final_kernel(const float* __restrict__ dgf_b,
                             const float* __restrict__ ln_g,
                             const float* __restrict__ ln_b,
                             float* __restrict__ out)
{
    __shared__ float sh[8];
    const size_t r = blockIdx.x;
    const int o = threadIdx.x;

    float sup = g_SUP[r * 256 + o];
    float as  = g_AS[r * 256 + o];
    float av  = g_AV[r * 256 + o];
    float pg0 = __half2float(g_Gh[r * 512 + o]);
    float pg1 = __half2float(g_Gh[r * 512 + 256 + o]);
    float gd  = 1.0f / (1.0f + expf(-(pg0 + g_biascat[o])));
    float gg  = 1.0f / (1.0f + expf(-(pg1 + g_biascat[256 + o])));

    float dense = gd * as + sup + dgf_b[o];
    float h = gg * av;

    float mean = block_sum_256(h, sh) * (1.0f / 256.0f);
    float d = h - mean;
    float var = block_sum_256(d * d, sh) * (1.0f / 256.0f);
    float gat = d * rsqrtf(var + 1e-5f) * ln_g[o] + ln_b[o];

    out[r * 256 + o] = 0.5f * (dense + gat);
}

// ---------------- launch ----------------
extern "C" void kernel_launch(void* const* d_in, const int* in_sizes, int n_in,
                              void* d_out, int out_size)
{
    const float* inputs  = (const float*)d_in[0];
    const float* adj     = (const float*)d_in[1];
    const float* op_emb  = (const float*)d_in[2];
    const float* dgf_W   = (const float*)d_in[3];
    const float* dgf_b   = (const float*)d_in[4];
    const float* dgf_opW = (const float*)d_in[5];
    const float* dgf_opb = (const float*)d_in[6];
    const float* Wk      = (const float*)d_in[7];
    const float* Wv      = (const float*)d_in[8];
    const float* Wq      = (const float*)d_in[9];
    const float* a_w     = (const float*)d_in[10];
    const float* gat_opW = (const float*)d_in[11];
    const float* gat_opb = (const float*)d_in[12];
    const float* ln_g    = (const float*)d_in[13];
    const float* ln_b    = (const float*)d_in[14];
    float* out = (float*)d_out;

    __half *W3, *Woph, *Xh, *OPh, *Yh, *SUPh, *WhvH, *Gh, *ATTh, *ADJh;
    float *SUP, *S, *AV, *AS;
    cudaGetSymbolAddress((void**)&W3,   g_W3);
    cudaGetSymbolAddress((void**)&Woph, g_Woph);
    cudaGetSymbolAddress((void**)&Xh,   g_Xh);
    cudaGetSymbolAddress((void**)&OPh,  g_OPh);
    cudaGetSymbolAddress((void**)&Yh,   g_Yh);
    cudaGetSymbolAddress((void**)&SUPh, g_SUPh);
    cudaGetSymbolAddress((void**)&WhvH, g_WhvH);
    cudaGetSymbolAddress((void**)&Gh,   g_Gh);
    cudaGetSymbolAddress((void**)&ATTh, g_attnh);
    cudaGetSymbolAddress((void**)&ADJh, g_adjh);
    cudaGetSymbolAddress((void**)&SUP,  g_SUP);
    cudaGetSymbolAddress((void**)&S,    g_S);
    cudaGetSymbolAddress((void**)&AV,   g_AV);
    cudaGetSymbolAddress((void**)&AS,   g_AS);

    const int DSMEM = 2 * STG1 * (int)sizeof(__half) + 256;   // 2 stages, ~74KB
    cudaFuncSetAttribute(gemm_h<0>, cudaFuncAttributeMaxDynamicSharedMemorySize, DSMEM);
    cudaFuncSetAttribute(gemm_h<1>, cudaFuncAttributeMaxDynamicSharedMemorySize, DSMEM);

    // weight prep
    mt_kernel<<<256, 256>>>(Wq, Wk, a_w);
    prep_kernel<<<512, 256>>>(dgf_W, Wv, dgf_opW, gat_opW, dgf_opb, gat_opb);
    // half copies of activations
    f2h_copy<<<(MTOT * DIN / 4 + 255) / 256, 256>>>((const float4*)inputs, (__half2*)Xh, MTOT * DIN / 4);
    f2h_copy<<<(MTOT * DOP / 4 + 255) / 256, 256>>>((const float4*)op_emb, (__half2*)OPh, MTOT * DOP / 4);

    // H: X @ [M | dgf_W | Wv]^T -> Yh | SUP(f32)+SUPh | WhvH   [32768 x 768]
    {
        dim3 grid(6, MTOT / 128, 1);
        gemm_h<0><<<grid, 256, DSMEM>>>(Xh, W3, SUP, Yh, SUPh, WhvH,
                                        256, 256, 256, 256, 4, 3, 0, 0, 0, 0);
    }
    // gates: OPh @ Woph^T -> Gh (half) [32768,512]
    {
        dim3 grid(4, MTOT / 128, 1);
        gemm_h<0><<<grid, 256, DSMEM>>>(OPh, Woph, SUP, Gh, SUPh, WhvH,
                                        64, 64, 0, 512, 1, 1, 0, 0, 0, 0);
    }
    // scores: S[b] = Y[b] @ X[b]^T -> fp32
    {
        dim3 grid(4, 4, BB);
        gemm_h<0><<<grid, 256, DSMEM>>>(Yh, Xh, S, Yh, SUPh, WhvH,
                                        256, 256, 512, 0, 4, 0,
                                        (size_t)512 * 256, (size_t)512 * 256, (size_t)512 * 512, 0);
    }
    // leaky + mask + softmax -> attn half; adj -> half
    softmax_kernel<<<MTOT, 256>>>(adj);

    // AV[b] = attn[b] @ Whv[b] -> fp32 [512,256]   (B row-major)
    {
        dim3 grid(2, 4, BB);
        gemm_h<1><<<grid, 256, DSMEM>>>(ATTh, WhvH, AV, Yh, SUPh, WhvH,
                                        512, 256, 256, 0, 8, 0,
                                        (size_t)512 * 512, (size_t)512 * 256, (size_t)512 * 256, 0);
    }
    // AS[b] = adj[b] @ support[b] -> fp32 [512,256]   (B row-major)
    {
        dim3 grid(2, 4, BB);
        gemm_h<1><<<grid, 256, DSMEM>>>(ADJh, SUPh, AS, Yh, SUPh, WhvH,
                                        512, 256, 256, 0, 8, 0,
                                        (size_t)512 * 512, (size_t)512 * 256, (size_t)512 * 256, 0);
    }
    // gates + residual + LN + blend
    final_kernel<<<MTOT, 256>>>(dgf_b, ln_g, ln_b, out);

    (void)in_sizes; (void)n_in; (void)out_size;
}

// round 13
// speedup vs baseline: 1.1959x; 1.1159x over previous
#include <cuda_runtime.h>
#include <cuda_fp16.h>
#include <mma.h>
#include <cstdint>

using namespace nvcuda;

// Problem dims
#define BB    64
#define NN    512
#define DIN   256
#define DOUTD 256
#define DOP   64
#define MTOT  (BB*NN)      // 32768

// ---------------- scratch (static device globals) ----------------
__device__ __half g_W3[768 * 256];                    // rows 0-255: M^T | 256-511: dgf_W^T | 512-767: Wv
__device__ __half g_Woph[512 * 64];                   // rows 0-255: dgf_opW | 256-511: gat_opW
__device__ float  g_biascat[512];
__device__ __half g_Xh[(size_t)MTOT * DIN];           // half inputs
__device__ __half g_OPh[(size_t)MTOT * DOP];          // half op_emb
__device__ __half g_Yh[(size_t)MTOT * 256];           // Y = X @ M (half)
__device__ float  g_SUP[(size_t)MTOT * 256];          // support (exact fp32)
__device__ __half g_SUPh[(size_t)MTOT * 256];         // support (half, for AS GEMM)
__device__ __half g_WhvH[(size_t)MTOT * 256];         // Whv (half, row-major, for AV GEMM)
__device__ __half g_Gh[(size_t)MTOT * 512];           // gate pre-acts (half)
__device__ float  g_S[(size_t)BB * NN * NN];          // scores (fp32)
__device__ __half g_attnh[(size_t)BB * NN * NN];      // softmax(attn) half
__device__ __half g_adjh[(size_t)BB * NN * NN];       // adj half
__device__ float  g_AV[(size_t)MTOT * 256];
__device__ float  g_AS[(size_t)MTOT * 256];

// ---------------- PTX helpers ----------------
__device__ __forceinline__ uint32_t smem_u32(const void* p) {
    uint32_t a;
    asm("{ .reg .u64 t; cvta.to.shared.u64 t, %1; cvt.u32.u64 %0, t; }" : "=r"(a) : "l"(p));
    return a;
}
__device__ __forceinline__ void cp16s(uint32_t dst, const void* src) {
    asm volatile("cp.async.cg.shared.global [%0], [%1], 16;" :: "r"(dst), "l"(src));
}

// ---------------- M^T precompute: g_W3[j,i] = sum_m Wq[m,i]*a_w[m]/16*Wk[m,j] ----------------
__global__ void mt_kernel(const float* __restrict__ Wq, const float* __restrict__ Wk,
                          const float* __restrict__ a_w)
{
    __shared__ float wk[256];
    const int j = blockIdx.x, i = threadIdx.x;
    wk[i] = Wk[i * 256 + j] * a_w[i] * 0.0625f;
    __syncthreads();
    float s = 0.0f;
#pragma unroll 8
    for (int m = 0; m < 256; m++) s += Wq[m * 256 + i] * wk[m];
    g_W3[j * 256 + i] = __float2half_rn(s);
}

// ---------------- prep: pack weights as half ----------------
__global__ void prep_kernel(const float* __restrict__ dgf_W,
                            const float* __restrict__ Wv,
                            const float* __restrict__ dgf_opW,
                            const float* __restrict__ gat_opW,
                            const float* __restrict__ dgf_opb,
                            const float* __restrict__ gat_opb)
{
    int idx = blockIdx.x * blockDim.x + threadIdx.x;
    if (idx < 512 * 256) {   // g_W3 rows 256-767
        int r = idx >> 8, i = idx & 255;
        float v = (r < 256) ? dgf_W[i * 256 + r]            // rows 256-511: dgf_W^T
                            : Wv[(r - 256) * 256 + i];      // rows 512-767: Wv
        g_W3[(256 + r) * 256 + i] = __float2half_rn(v);
    }
    if (idx < 512 * 64) {
        int n = idx >> 6, p = idx & 63;
        float v = (n < 256) ? dgf_opW[n * 64 + p] : gat_opW[(n - 256) * 64 + p];
        g_Woph[idx] = __float2half_rn(v);
    }
    if (idx < 512) {
        g_biascat[idx] = (idx < 256) ? dgf_opb[idx] : gat_opb[idx - 256];
    }
}

// ---------------- float -> half copy ----------------
__global__ void f2h_copy(const float4* __restrict__ src, __half2* __restrict__ dst, int n4)
{
    int i = blockIdx.x * blockDim.x + threadIdx.x;
    if (i < n4) {
        float4 v = src[i];
        dst[2 * i]     = __floats2half2_rn(v.x, v.y);
        dst[2 * i + 1] = __floats2half2_rn(v.z, v.w);
    }
}

// ---------------- fp16 wmma GEMM: 128x128 CTA, 4 warps (2x2), 64x64 warp tile ----------------
// 128 threads/CTA, 2 CTAs/SM, BK=64, 2-stage cp.async pipeline.
// BROW=0: C = A @ B^T, B row-major [N,K] (K contiguous)
// BROW=1: C = A @ B,   B row-major [K,N] (N contiguous)
// mode 0: fp32 -> Cf. mode 1: half -> Ch.
// mode 3 (H kernel, N=768): col<256 -> Ch(Yh); col<512 -> Cf(SUP,fp32)+Ch2(SUPh,half); else -> Ch3(WhvH,half)
// Dual-problem launch: if blockIdx.z >= zsplit, switch to (A2,B2,Cf2) with z -= zsplit.
constexpr int BKH = 64;
constexpr int LDH = 72;                    // A / BROW0-B smem stride (halfs)
constexpr int LDB_R = 136;                 // BROW1-B smem stride (halfs)
constexpr int ASTG = 128 * LDH;            // 9216 halfs
constexpr int BSTG = 9216;                 // B stage region (BROW0:128*72=9216, BROW1:64*136=8704)
constexpr int STG1 = ASTG + BSTG;          // halfs per stage

template <int BROW>
__global__ __launch_bounds__(128, 2)
void gemm_h(const __half* __restrict__ A, const __half* __restrict__ B,
            float* __restrict__ Cf, __half* __restrict__ Ch,
            __half* __restrict__ Ch2, __half* __restrict__ Ch3,
            const __half* __restrict__ A2, const __half* __restrict__ B2,
            float* __restrict__ Cf2, int zsplit,
            int lda, int ldb, int ldcf, int ldch, int T, int mode,
            size_t sA, size_t sB, size_t sCf, size_t sCh)
{
    extern __shared__ __half smraw[];
    __half* sm = (__half*)(((uintptr_t)smraw + 127) & ~(uintptr_t)127);

    int z = blockIdx.z;
    if (z >= zsplit) { z -= zsplit; A = A2; B = B2; Cf = Cf2; }
    A += (size_t)z * sA;
    B += (size_t)z * sB;
    Cf += (size_t)z * sCf;
    Ch += (size_t)z * sCh;

    const int bm = blockIdx.y * 128, bn = blockIdx.x * 128;
    const int tid = threadIdx.x, warp = tid >> 5;
    const int wm = (warp >> 1) * 64;       // 2 warp rows x 64
    const int wn = (warp & 1) * 64;        // 2 warp cols x 64

    wmma::fragment<wmma::accumulator, 16, 16, 16, float> acc[4][4];
#pragma unroll
    for (int i = 0; i < 4; i++)
#pragma unroll
        for (int j = 0; j < 4; j++) wmma::fill_fragment(acc[i][j], 0.0f);

    auto load_stage = [&](int s, int t) {
        __half* as = sm + (size_t)s * STG1;
        __half* bs = as + ASTG;
        const int k0 = t * BKH;
#pragma unroll
        for (int it = 0; it < 8; it++) {     // A: 128 rows x 64 halfs = 1024 cp16
            int idx = tid + it * 128;
            int rr = idx >> 3, cc = idx & 7;
            cp16s(smem_u32(as + rr * LDH + cc * 8),
                  A + (size_t)(bm + rr) * lda + k0 + cc * 8);
        }
        if (BROW == 0) {
#pragma unroll
            for (int it = 0; it < 8; it++) { // B: 128 N-rows x 64 halfs (K contig)
                int idx = tid + it * 128;
                int rr = idx >> 3, cc = idx & 7;
                cp16s(smem_u32(bs + rr * LDH + cc * 8),
                      B + (size_t)(bn + rr) * ldb + k0 + cc * 8);
            }
        } else {
#pragma unroll
            for (int it = 0; it < 8; it++) { // B: 64 K-rows x 128 halfs (N contig)
                int idx = tid + it * 128;
                int rr = idx >> 4, cc = idx & 15;
                cp16s(smem_u32(bs + rr * LDB_R + cc * 8),
                      B + (size_t)(k0 + rr) * ldb + bn + cc * 8);
            }
        }
        asm volatile("cp.async.commit_group;");
    };

    load_stage(0, 0);

    for (int t = 0; t < T; t++) {
        const int s = t & 1;
        if (t + 1 < T) {
            load_stage(s ^ 1, t + 1);
            asm volatile("cp.async.wait_group 1;");
        } else {
            asm volatile("cp.async.wait_group 0;");
        }
        __syncthreads();

        const __half* as = sm + (size_t)s * STG1;
        const __half* bs = as + ASTG;
#pragma unroll
        for (int kk = 0; kk < BKH; kk += 16) {
            wmma::fragment<wmma::matrix_a, 16, 16, 16, __half, wmma::row_major> af[4];
#pragma unroll
            for (int ii = 0; ii < 4; ii++)
                wmma::load_matrix_sync(af[ii], as + (wm + 16 * ii) * LDH + kk, LDH);
            if (BROW == 0) {
                wmma::fragment<wmma::matrix_b, 16, 16, 16, __half, wmma::col_major> bf[4];
#pragma unroll
                for (int j = 0; j < 4; j++)
                    wmma::load_matrix_sync(bf[j], bs + (wn + 16 * j) * LDH + kk, LDH);
#pragma unroll
                for (int ii = 0; ii < 4; ii++)
#pragma unroll
                    for (int j = 0; j < 4; j++)
                        wmma::mma_sync(acc[ii][j], af[ii], bf[j], acc[ii][j]);
            } else {
                wmma::fragment<wmma::matrix_b, 16, 16, 16, __half, wmma::row_major> bf[4];
#pragma unroll
                for (int j = 0; j < 4; j++)
                    wmma::load_matrix_sync(bf[j], bs + kk * LDB_R + wn + 16 * j, LDB_R);
#pragma unroll
                for (int ii = 0; ii < 4; ii++)
#pragma unroll
                    for (int j = 0; j < 4; j++)
                        wmma::mma_sync(acc[ii][j], af[ii], bf[j], acc[ii][j]);
            }
        }
        __syncthreads();
    }

    // ---- epilogue ----
#pragma unroll
    for (int ii = 0; ii < 4; ii++)
#pragma unroll
        for (int j = 0; j < 4; j++) {
            const int row = bm + wm + 16 * ii;
            const int col = bn + wn + 16 * j;
            if (mode == 0) {
                wmma::store_matrix_sync(Cf + (size_t)row * ldcf + col, acc[ii][j], ldcf,
                                        wmma::mem_row_major);
            } else if (mode == 1) {
                wmma::fragment<wmma::accumulator, 16, 16, 16, __half> hf;
#pragma unroll
                for (int t = 0; t < hf.num_elements; t++)
                    hf.x[t] = __float2half_rn(acc[ii][j].x[t]);
                wmma::store_matrix_sync(Ch + (size_t)row * ldch + col, hf, ldch,
                                        wmma::mem_row_major);
            } else {  // mode 3: H triple output
                if (col < 256) {
                    wmma::fragment<wmma::accumulator, 16, 16, 16, __half> hf;
#pragma unroll
                    for (int t = 0; t < hf.num_elements; t++)
                        hf.x[t] = __float2half_rn(acc[ii][j].x[t]);
                    wmma::store_matrix_sync(Ch + (size_t)row * 256 + col, hf, 256,
                                            wmma::mem_row_major);
                } else if (col < 512) {
                    wmma::store_matrix_sync(Cf + (size_t)row * 256 + (col - 256), acc[ii][j], 256,
                                            wmma::mem_row_major);
                    wmma::fragment<wmma::accumulator, 16, 16, 16, __half> hf;
#pragma unroll
                    for (int t = 0; t < hf.num_elements; t++)
                        hf.x[t] = __float2half_rn(acc[ii][j].x[t]);
                    wmma::store_matrix_sync(Ch2 + (size_t)row * 256 + (col - 256), hf, 256,
                                            wmma::mem_row_major);
                } else {
                    wmma::fragment<wmma::accumulator, 16, 16, 16, __half> hf;
#pragma unroll
                    for (int t = 0; t < hf.num_elements; t++)
                        hf.x[t] = __float2half_rn(acc[ii][j].x[t]);
                    wmma::store_matrix_sync(Ch3 + (size_t)row * 256 + (col - 512), hf, 256,
                                            wmma::mem_row_major);
                }
            }
        }
}

// ---------------- reductions ----------------
__device__ __forceinline__ float warp_max(float v) {
#pragma unroll
    for (int o = 16; o; o >>= 1) v = fmaxf(v, __shfl_xor_sync(0xffffffffu, v, o));
    return v;
}
__device__ __forceinline__ float warp_sum(float v) {
#pragma unroll
    for (int o = 16; o; o >>= 1) v += __shfl_xor_sync(0xffffffffu, v, o);
    return v;
}
__device__ __forceinline__ float block_max_256(float v, float* sh) {
    float w = warp_max(v);
    __syncthreads();
    if ((threadIdx.x & 31) == 0) sh[threadIdx.x >> 5] = w;
    __syncthreads();
    float t = sh[0];
#pragma unroll
    for (int i = 1; i < 8; i++) t = fmaxf(t, sh[i]);
    return t;
}
__device__ __forceinline__ float block_sum_256(float v, float* sh) {
    float w = warp_sum(v);
    __syncthreads();
    if ((threadIdx.x & 31) == 0) sh[threadIdx.x >> 5] = w;
    __syncthreads();
    float t = 0.0f;
#pragma unroll
    for (int i = 0; i < 8; i++) t += sh[i];
    return t;
}

// ------- leaky+mask+softmax over rows of S -> attn (half); also emit adj (half) -------
__global__ void softmax_kernel(const float* __restrict__ adj)
{
    __shared__ float sh[8];
    const int r = blockIdx.x;
    const float* Srow = g_S + (size_t)r * NN;
    const float* arow = adj + (size_t)r * NN;
    __half* Orow = g_attnh + (size_t)r * NN;
    __half* Arow = g_adjh + (size_t)r * NN;
    const int t = threadIdx.x;

    float v0 = Srow[t], v1 = Srow[t + 256];
    float a0 = arow[t], a1 = arow[t + 256];
    Arow[t]       = __float2half_rn(a0);
    Arow[t + 256] = __float2half_rn(a1);
    v0 = (v0 >= 0.0f ? v0 : 0.2f * v0) * a0;
    v1 = (v1 >= 0.0f ? v1 : 0.2f * v1) * a1;

    float m = block_max_256(fmaxf(v0, v1), sh);
    float e0 = expf(v0 - m), e1 = expf(v1 - m);
    float s = block_sum_256(e0 + e1, sh);
    float inv = 1.0f / s;
    Orow[t]       = __float2half_rn(e0 * inv);
    Orow[t + 256] = __float2half_rn(e1 * inv);
}

// ---------------- final: gates + dense residual + LN + blend ----------------
__global__ void final_kernel(const float* __restrict__ dgf_b,
                             const float* __restrict__ ln_g,
                             const float* __restrict__ ln_b,
                             float* __restrict__ out)
{
    __shared__ float sh[8];
    const size_t r = blockIdx.x;
    const int o = threadIdx.x;

    float sup = g_SUP[r * 256 + o];
    float as  = g_AS[r * 256 + o];
    float av  = g_AV[r * 256 + o];
    float pg0 = __half2float(g_Gh[r * 512 + o]);
    float pg1 = __half2float(g_Gh[r * 512 + 256 + o]);
    float gd  = 1.0f / (1.0f + expf(-(pg0 + g_biascat[o])));
    float gg  = 1.0f / (1.0f + expf(-(pg1 + g_biascat[256 + o])));

    float dense = gd * as + sup + dgf_b[o];
    float h = gg * av;

    float mean = block_sum_256(h, sh) * (1.0f / 256.0f);
    float d = h - mean;
    float var = block_sum_256(d * d, sh) * (1.0f / 256.0f);
    float gat = d * rsqrtf(var + 1e-5f) * ln_g[o] + ln_b[o];

    out[r * 256 + o] = 0.5f * (dense + gat);
}

// ---------------- launch ----------------
extern "C" void kernel_launch(void* const* d_in, const int* in_sizes, int n_in,
                              void* d_out, int out_size)
{
    const float* inputs  = (const float*)d_in[0];
    const float* adj     = (const float*)d_in[1];
    const float* op_emb  = (const float*)d_in[2];
    const float* dgf_W   = (const float*)d_in[3];
    const float* dgf_b   = (const float*)d_in[4];
    const float* dgf_opW = (const float*)d_in[5];
    const float* dgf_opb = (const float*)d_in[6];
    const float* Wk      = (const float*)d_in[7];
    const float* Wv      = (const float*)d_in[8];
    const float* Wq      = (const float*)d_in[9];
    const float* a_w     = (const float*)d_in[10];
    const float* gat_opW = (const float*)d_in[11];
    const float* gat_opb = (const float*)d_in[12];
    const float* ln_g    = (const float*)d_in[13];
    const float* ln_b    = (const float*)d_in[14];
    float* out = (float*)d_out;

    __half *W3, *Woph, *Xh, *OPh, *Yh, *SUPh, *WhvH, *Gh, *ATTh, *ADJh;
    float *SUP, *S, *AV, *AS;
    cudaGetSymbolAddress((void**)&W3,   g_W3);
    cudaGetSymbolAddress((void**)&Woph, g_Woph);
    cudaGetSymbolAddress((void**)&Xh,   g_Xh);
    cudaGetSymbolAddress((void**)&OPh,  g_OPh);
    cudaGetSymbolAddress((void**)&Yh,   g_Yh);
    cudaGetSymbolAddress((void**)&SUPh, g_SUPh);
    cudaGetSymbolAddress((void**)&WhvH, g_WhvH);
    cudaGetSymbolAddress((void**)&Gh,   g_Gh);
    cudaGetSymbolAddress((void**)&ATTh, g_attnh);
    cudaGetSymbolAddress((void**)&ADJh, g_adjh);
    cudaGetSymbolAddress((void**)&SUP,  g_SUP);
    cudaGetSymbolAddress((void**)&S,    g_S);
    cudaGetSymbolAddress((void**)&AV,   g_AV);
    cudaGetSymbolAddress((void**)&AS,   g_AS);

    const int DSMEM = 2 * STG1 * (int)sizeof(__half) + 256;   // 2 stages, ~74KB
    cudaFuncSetAttribute(gemm_h<0>, cudaFuncAttributeMaxDynamicSharedMemorySize, DSMEM);
    cudaFuncSetAttribute(gemm_h<1>, cudaFuncAttributeMaxDynamicSharedMemorySize, DSMEM);

    // weight prep
    mt_kernel<<<256, 256>>>(Wq, Wk, a_w);
    prep_kernel<<<512, 256>>>(dgf_W, Wv, dgf_opW, gat_opW, dgf_opb, gat_opb);
    // half copies of activations
    f2h_copy<<<(MTOT * DIN / 4 + 255) / 256, 256>>>((const float4*)inputs, (__half2*)Xh, MTOT * DIN / 4);
    f2h_copy<<<(MTOT * DOP / 4 + 255) / 256, 256>>>((const float4*)op_emb, (__half2*)OPh, MTOT * DOP / 4);

    // H: X @ [M | dgf_W | Wv]^T -> Yh | SUP(f32)+SUPh | WhvH   [32768 x 768]
    {
        dim3 grid(6, MTOT / 128, 1);
        gemm_h<0><<<grid, 128, DSMEM>>>(Xh, W3, SUP, Yh, SUPh, WhvH,
                                        Xh, W3, SUP, 1 << 30,
                                        256, 256, 256, 256, 4, 3, 0, 0, 0, 0);
    }
    // gates: OPh @ Woph^T -> Gh (half) [32768,512]
    {
        dim3 grid(4, MTOT / 128, 1);
        gemm_h<0><<<grid, 128, DSMEM>>>(OPh, Woph, SUP, Gh, SUPh, WhvH,
                                        OPh, Woph, SUP, 1 << 30,
                                        64, 64, 0, 512, 1, 1, 0, 0, 0, 0);
    }
    // scores: S[b] = Y[b] @ X[b]^T -> fp32
    {
        dim3 grid(4, 4, BB);
        gemm_h<0><<<grid, 128, DSMEM>>>(Yh, Xh, S, Yh, SUPh, WhvH,
                                        Yh, Xh, S, 1 << 30,
                                        256, 256, 512, 0, 4, 0,
                                        (size_t)512 * 256, (size_t)512 * 256, (size_t)512 * 512, 0);
    }
    // leaky + mask + softmax -> attn half; adj -> half
    softmax_kernel<<<MTOT, 256>>>(adj);

    // AV[b] = attn[b] @ Whv[b]  (z<64)   AS[b] = adj[b] @ support[b]  (z>=64)  -> fp32 [512,256]
    {
        dim3 grid(2, 4, 2 * BB);
        gemm_h<1><<<grid, 128, DSMEM>>>(ATTh, WhvH, AV, Yh, SUPh, WhvH,
                                        ADJh, SUPh, AS, BB,
                                        512, 256, 256, 0, 8, 0,
                                        (size_t)512 * 512, (size_t)512 * 256, (size_t)512 * 256, 0);
    }
    // gates + residual + LN + blend
    final_kernel<<<MTOT, 256>>>(dgf_b, ln_g, ln_b, out);

    (void)in_sizes; (void)n_in; (void)out_size;
}

// round 14
// speedup vs baseline: 1.2905x; 1.0791x over previous
#include <cuda_runtime.h>
#include <cuda_fp16.h>
#include <mma.h>
#include <cstdint>

using namespace nvcuda;

// Problem dims
#define BB    64
#define NN    512
#define DIN   256
#define DOUTD 256
#define DOP   64
#define MTOT  (BB*NN)      // 32768

// ---------------- scratch (static device globals) ----------------
__device__ __half g_W3[768 * 256];                    // rows 0-255: M^T | 256-511: dgf_W^T | 512-767: Wv
__device__ __half g_Woph[512 * 64];                   // rows 0-255: dgf_opW | 256-511: gat_opW
__device__ float  g_biascat[512];
__device__ __half g_Xh[(size_t)MTOT * DIN];           // half inputs
__device__ __half g_OPh[(size_t)MTOT * DOP];          // half op_emb
__device__ __half g_Yh[(size_t)MTOT * 256];           // Y = X @ M (half)
__device__ float  g_SUP[(size_t)MTOT * 256];          // support (exact fp32)
__device__ __half g_SUPh[(size_t)MTOT * 256];         // support (half, for AS GEMM)
__device__ __half g_WhvH[(size_t)MTOT * 256];         // Whv (half, row-major, for AV GEMM)
__device__ __half g_Gh[(size_t)MTOT * 512];           // gate pre-acts (half)
__device__ float  g_S[(size_t)BB * NN * NN];          // scores (fp32)
__device__ __half g_attnh[(size_t)BB * NN * NN];      // softmax(attn) half
__device__ __half g_adjh[(size_t)BB * NN * NN];       // adj half
__device__ float  g_AV[(size_t)MTOT * 256];
__device__ float  g_AS[(size_t)MTOT * 256];

// ---------------- PTX helpers ----------------
__device__ __forceinline__ uint32_t smem_u32(const void* p) {
    uint32_t a;
    asm("{ .reg .u64 t; cvta.to.shared.u64 t, %1; cvt.u32.u64 %0, t; }" : "=r"(a) : "l"(p));
    return a;
}
__device__ __forceinline__ void cp16s(uint32_t dst, const void* src) {
    asm volatile("cp.async.cg.shared.global [%0], [%1], 16;" :: "r"(dst), "l"(src));
}

// ---------------- M^T precompute: g_W3[j,i] = sum_m Wq[m,i]*a_w[m]/16*Wk[m,j] ----------------
__global__ void mt_kernel(const float* __restrict__ Wq, const float* __restrict__ Wk,
                          const float* __restrict__ a_w)
{
    __shared__ float wk[256];
    const int j = blockIdx.x, i = threadIdx.x;
    wk[i] = Wk[i * 256 + j] * a_w[i] * 0.0625f;
    __syncthreads();
    float s = 0.0f;
#pragma unroll 8
    for (int m = 0; m < 256; m++) s += Wq[m * 256 + i] * wk[m];
    g_W3[j * 256 + i] = __float2half_rn(s);
}

// ---------------- prep: pack weights as half ----------------
__global__ void prep_kernel(const float* __restrict__ dgf_W,
                            const float* __restrict__ Wv,
                            const float* __restrict__ dgf_opW,
                            const float* __restrict__ gat_opW,
                            const float* __restrict__ dgf_opb,
                            const float* __restrict__ gat_opb)
{
    int idx = blockIdx.x * blockDim.x + threadIdx.x;
    if (idx < 512 * 256) {   // g_W3 rows 256-767
        int r = idx >> 8, i = idx & 255;
        float v = (r < 256) ? dgf_W[i * 256 + r]            // rows 256-511: dgf_W^T
                            : Wv[(r - 256) * 256 + i];      // rows 512-767: Wv
        g_W3[(256 + r) * 256 + i] = __float2half_rn(v);
    }
    if (idx < 512 * 64) {
        int n = idx >> 6, p = idx & 63;
        float v = (n < 256) ? dgf_opW[n * 64 + p] : gat_opW[(n - 256) * 64 + p];
        g_Woph[idx] = __float2half_rn(v);
    }
    if (idx < 512) {
        g_biascat[idx] = (idx < 256) ? dgf_opb[idx] : gat_opb[idx - 256];
    }
}

// ---------------- float -> half copy ----------------
__global__ void f2h_copy(const float4* __restrict__ src, __half2* __restrict__ dst, int n4)
{
    int i = blockIdx.x * blockDim.x + threadIdx.x;
    if (i < n4) {
        float4 v = src[i];
        dst[2 * i]     = __floats2half2_rn(v.x, v.y);
        dst[2 * i + 1] = __floats2half2_rn(v.z, v.w);
    }
}

// ---------------- fp16 wmma GEMM: 128x128 CTA, 4 warps (2x2), 64x64 warp tile ----------------
// 128 threads/CTA, 2 CTAs/SM, BK=64, 2-stage cp.async pipeline.
// BROW=0: C = A @ B^T, B row-major [N,K] (K contiguous)
// BROW=1: C = A @ B,   B row-major [K,N] (N contiguous)
// mode 0: fp32 -> Cf. mode 1: half -> Ch.
// mode 3 (H kernel): col<256 -> Ch(Yh); col<512 -> Cf(SUP,fp32)+Ch2(SUPh,half); else -> Ch3(WhvH,half)
// z-split: blockIdx.z >= zsplit -> (A2,B2,Cf2), z -= zsplit (same shape params).
// x-split: blockIdx.x >= xsplit -> second problem (Ax,Bx,Chx, ldax,ldbx,Tx,modex,ldchx).
constexpr int BKH = 64;
constexpr int LDH = 72;                    // A / BROW0-B smem stride (halfs)
constexpr int LDB_R = 136;                 // BROW1-B smem stride (halfs)
constexpr int ASTG = 128 * LDH;            // 9216 halfs
constexpr int BSTG = 9216;                 // B stage region (BROW0:128*72=9216, BROW1:64*136=8704)
constexpr int STG1 = ASTG + BSTG;          // halfs per stage

template <int BROW>
__global__ __launch_bounds__(128, 2)
void gemm_h(const __half* __restrict__ A, const __half* __restrict__ B,
            float* __restrict__ Cf, __half* __restrict__ Ch,
            __half* __restrict__ Ch2, __half* __restrict__ Ch3,
            const __half* __restrict__ A2, const __half* __restrict__ B2,
            float* __restrict__ Cf2, int zsplit,
            const __half* __restrict__ Ax, const __half* __restrict__ Bx,
            __half* __restrict__ Chx, int xsplit,
            int ldax, int ldbx, int Tx, int modex, int ldchx,
            int lda, int ldb, int ldcf, int ldch, int T, int mode,
            size_t sA, size_t sB, size_t sCf, size_t sCh)
{
    extern __shared__ __half smraw[];
    __half* sm = (__half*)(((uintptr_t)smraw + 127) & ~(uintptr_t)127);

    int z = blockIdx.z;
    if (z >= zsplit) { z -= zsplit; A = A2; B = B2; Cf = Cf2; }
    int bx = blockIdx.x;
    if (bx >= xsplit) {
        bx -= xsplit;
        A = Ax; B = Bx; Ch = Chx;
        lda = ldax; ldb = ldbx; T = Tx; mode = modex; ldch = ldchx;
    }
    A += (size_t)z * sA;
    B += (size_t)z * sB;
    Cf += (size_t)z * sCf;
    Ch += (size_t)z * sCh;

    const int bm = blockIdx.y * 128, bn = bx * 128;
    const int tid = threadIdx.x, warp = tid >> 5;
    const int wm = (warp >> 1) * 64;       // 2 warp rows x 64
    const int wn = (warp & 1) * 64;        // 2 warp cols x 64

    wmma::fragment<wmma::accumulator, 16, 16, 16, float> acc[4][4];
#pragma unroll
    for (int i = 0; i < 4; i++)
#pragma unroll
        for (int j = 0; j < 4; j++) wmma::fill_fragment(acc[i][j], 0.0f);

    auto load_stage = [&](int s, int t) {
        __half* as = sm + (size_t)s * STG1;
        __half* bs = as + ASTG;
        const int k0 = t * BKH;
#pragma unroll
        for (int it = 0; it < 8; it++) {     // A: 128 rows x 64 halfs = 1024 cp16
            int idx = tid + it * 128;
            int rr = idx >> 3, cc = idx & 7;
            cp16s(smem_u32(as + rr * LDH + cc * 8),
                  A + (size_t)(bm + rr) * lda + k0 + cc * 8);
        }
        if (BROW == 0) {
#pragma unroll
            for (int it = 0; it < 8; it++) { // B: 128 N-rows x 64 halfs (K contig)
                int idx = tid + it * 128;
                int rr = idx >> 3, cc = idx & 7;
                cp16s(smem_u32(bs + rr * LDH + cc * 8),
                      B + (size_t)(bn + rr) * ldb + k0 + cc * 8);
            }
        } else {
#pragma unroll
            for (int it = 0; it < 8; it++) { // B: 64 K-rows x 128 halfs (N contig)
                int idx = tid + it * 128;
                int rr = idx >> 4, cc = idx & 15;
                cp16s(smem_u32(bs + rr * LDB_R + cc * 8),
                      B + (size_t)(k0 + rr) * ldb + bn + cc * 8);
            }
        }
        asm volatile("cp.async.commit_group;");
    };

    load_stage(0, 0);

    for (int t = 0; t < T; t++) {
        const int s = t & 1;
        if (t + 1 < T) {
            load_stage(s ^ 1, t + 1);
            asm volatile("cp.async.wait_group 1;");
        } else {
            asm volatile("cp.async.wait_group 0;");
        }
        __syncthreads();

        const __half* as = sm + (size_t)s * STG1;
        const __half* bs = as + ASTG;
#pragma unroll
        for (int kk = 0; kk < BKH; kk += 16) {
            wmma::fragment<wmma::matrix_a, 16, 16, 16, __half, wmma::row_major> af[4];
#pragma unroll
            for (int ii = 0; ii < 4; ii++)
                wmma::load_matrix_sync(af[ii], as + (wm + 16 * ii) * LDH + kk, LDH);
            if (BROW == 0) {
                wmma::fragment<wmma::matrix_b, 16, 16, 16, __half, wmma::col_major> bf[4];
#pragma unroll
                for (int j = 0; j < 4; j++)
                    wmma::load_matrix_sync(bf[j], bs + (wn + 16 * j) * LDH + kk, LDH);
#pragma unroll
                for (int ii = 0; ii < 4; ii++)
#pragma unroll
                    for (int j = 0; j < 4; j++)
                        wmma::mma_sync(acc[ii][j], af[ii], bf[j], acc[ii][j]);
            } else {
                wmma::fragment<wmma::matrix_b, 16, 16, 16, __half, wmma::row_major> bf[4];
#pragma unroll
                for (int j = 0; j < 4; j++)
                    wmma::load_matrix_sync(bf[j], bs + kk * LDB_R + wn + 16 * j, LDB_R);
#pragma unroll
                for (int ii = 0; ii < 4; ii++)
#pragma unroll
                    for (int j = 0; j < 4; j++)
                        wmma::mma_sync(acc[ii][j], af[ii], bf[j], acc[ii][j]);
            }
        }
        __syncthreads();
    }

    // ---- epilogue ----
#pragma unroll
    for (int ii = 0; ii < 4; ii++)
#pragma unroll
        for (int j = 0; j < 4; j++) {
            const int row = bm + wm + 16 * ii;
            const int col = bn + wn + 16 * j;
            if (mode == 0) {
                wmma::store_matrix_sync(Cf + (size_t)row * ldcf + col, acc[ii][j], ldcf,
                                        wmma::mem_row_major);
            } else if (mode == 1) {
                wmma::fragment<wmma::accumulator, 16, 16, 16, __half> hf;
#pragma unroll
                for (int t = 0; t < hf.num_elements; t++)
                    hf.x[t] = __float2half_rn(acc[ii][j].x[t]);
                wmma::store_matrix_sync(Ch + (size_t)row * ldch + col, hf, ldch,
                                        wmma::mem_row_major);
            } else {  // mode 3: H triple output
                if (col < 256) {
                    wmma::fragment<wmma::accumulator, 16, 16, 16, __half> hf;
#pragma unroll
                    for (int t = 0; t < hf.num_elements; t++)
                        hf.x[t] = __float2half_rn(acc[ii][j].x[t]);
                    wmma::store_matrix_sync(Ch + (size_t)row * 256 + col, hf, 256,
                                            wmma::mem_row_major);
                } else if (col < 512) {
                    wmma::store_matrix_sync(Cf + (size_t)row * 256 + (col - 256), acc[ii][j], 256,
                                            wmma::mem_row_major);
                    wmma::fragment<wmma::accumulator, 16, 16, 16, __half> hf;
#pragma unroll
                    for (int t = 0; t < hf.num_elements; t++)
                        hf.x[t] = __float2half_rn(acc[ii][j].x[t]);
                    wmma::store_matrix_sync(Ch2 + (size_t)row * 256 + (col - 256), hf, 256,
                                            wmma::mem_row_major);
                } else {
                    wmma::fragment<wmma::accumulator, 16, 16, 16, __half> hf;
#pragma unroll
                    for (int t = 0; t < hf.num_elements; t++)
                        hf.x[t] = __float2half_rn(acc[ii][j].x[t]);
                    wmma::store_matrix_sync(Ch3 + (size_t)row * 256 + (col - 512), hf, 256,
                                            wmma::mem_row_major);
                }
            }
        }
}

// ---------------- warp reductions ----------------
__device__ __forceinline__ float warp_max(float v) {
#pragma unroll
    for (int o = 16; o; o >>= 1) v = fmaxf(v, __shfl_xor_sync(0xffffffffu, v, o));
    return v;
}
__device__ __forceinline__ float warp_sum(float v) {
#pragma unroll
    for (int o = 16; o; o >>= 1) v += __shfl_xor_sync(0xffffffffu, v, o);
    return v;
}

// ------- leaky+mask+softmax: 2 rows/block, 128 thr/row, float4 per thread -------
__global__ void softmax_kernel(const float* __restrict__ adj)
{
    __shared__ float sh[2][4];
    const int rw = threadIdx.x >> 7;                 // row within block (0/1)
    const int t = threadIdx.x & 127;                 // col-thread (4 cols each)
    const int wip = (threadIdx.x >> 5) & 3;          // warp within row
    const size_t r = (size_t)blockIdx.x * 2 + rw;

    float4 v = *(const float4*)(g_S + r * NN + t * 4);
    float4 a = *(const float4*)(adj + r * NN + t * 4);

    // adj -> half (8B store)
    {
        __half2 h01 = __floats2half2_rn(a.x, a.y);
        __half2 h23 = __floats2half2_rn(a.z, a.w);
        uint2 u = make_uint2(*(unsigned*)&h01, *(unsigned*)&h23);
        *(uint2*)(g_adjh + r * NN + t * 4) = u;
    }

    v.x = (v.x >= 0.0f ? v.x : 0.2f * v.x) * a.x;
    v.y = (v.y >= 0.0f ? v.y : 0.2f * v.y) * a.y;
    v.z = (v.z >= 0.0f ? v.z : 0.2f * v.z) * a.z;
    v.w = (v.w >= 0.0f ? v.w : 0.2f * v.w) * a.w;

    float m = fmaxf(fmaxf(v.x, v.y), fmaxf(v.z, v.w));
    m = warp_max(m);
    if ((threadIdx.x & 31) == 0) sh[rw][wip] = m;
    __syncthreads();
    m = fmaxf(fmaxf(sh[rw][0], sh[rw][1]), fmaxf(sh[rw][2], sh[rw][3]));

    float e0 = expf(v.x - m), e1 = expf(v.y - m), e2 = expf(v.z - m), e3 = expf(v.w - m);
    float s = warp_sum(e0 + e1 + e2 + e3);
    __syncthreads();
    if ((threadIdx.x & 31) == 0) sh[rw][wip] = s;
    __syncthreads();
    s = sh[rw][0] + sh[rw][1] + sh[rw][2] + sh[rw][3];
    float inv = 1.0f / s;

    __half2 o01 = __floats2half2_rn(e0 * inv, e1 * inv);
    __half2 o23 = __floats2half2_rn(e2 * inv, e3 * inv);
    uint2 u = make_uint2(*(unsigned*)&o01, *(unsigned*)&o23);
    *(uint2*)(g_attnh + r * NN + t * 4) = u;
}

// ---------------- final: 4 rows/block, 64 thr/row, float4 per thread ----------------
__global__ void final_kernel(const float* __restrict__ dgf_b,
                             const float* __restrict__ ln_g,
                             const float* __restrict__ ln_b,
                             float* __restrict__ out)
{
    __shared__ float sh[4][2];
    const int rw = threadIdx.x >> 6;                 // row within block (0..3)
    const int t = threadIdx.x & 63;                  // col-thread (4 cols each)
    const int wip = (threadIdx.x >> 5) & 1;          // warp within row
    const size_t r = (size_t)blockIdx.x * 4 + rw;
    const int c = t * 4;

    float4 sup = *(const float4*)(g_SUP + r * 256 + c);
    float4 as  = *(const float4*)(g_AS + r * 256 + c);
    float4 av  = *(const float4*)(g_AV + r * 256 + c);
    uint2 ug0 = *(const uint2*)(g_Gh + r * 512 + c);
    uint2 ug1 = *(const uint2*)(g_Gh + r * 512 + 256 + c);
    float4 bc0, bc1;
    bc0 = *(const float4*)(g_biascat + c);
    bc1 = *(const float4*)(g_biascat + 256 + c);
    float4 db = *(const float4*)(dgf_b + c);
    float4 lg = *(const float4*)(ln_g + c);
    float4 lb = *(const float4*)(ln_b + c);

    float2 g0a = __half22float2(*(__half2*)&ug0.x);
    float2 g0b = __half22float2(*(__half2*)&ug0.y);
    float2 g1a = __half22float2(*(__half2*)&ug1.x);
    float2 g1b = __half22float2(*(__half2*)&ug1.y);

    float gd0 = 1.0f / (1.0f + expf(-(g0a.x + bc0.x)));
    float gd1 = 1.0f / (1.0f + expf(-(g0a.y + bc0.y)));
    float gd2 = 1.0f / (1.0f + expf(-(g0b.x + bc0.z)));
    float gd3 = 1.0f / (1.0f + expf(-(g0b.y + bc0.w)));
    float gg0 = 1.0f / (1.0f + expf(-(g1a.x + bc1.x)));
    float gg1 = 1.0f / (1.0f + expf(-(g1a.y + bc1.y)));
    float gg2 = 1.0f / (1.0f + expf(-(g1b.x + bc1.z)));
    float gg3 = 1.0f / (1.0f + expf(-(g1b.y + bc1.w)));

    float d0 = gd0 * as.x + sup.x + db.x;
    float d1 = gd1 * as.y + sup.y + db.y;
    float d2 = gd2 * as.z + sup.z + db.z;
    float d3 = gd3 * as.w + sup.w + db.w;

    float h0 = gg0 * av.x, h1 = gg1 * av.y, h2 = gg2 * av.z, h3 = gg3 * av.w;

    float s = warp_sum(h0 + h1 + h2 + h3);
    if ((threadIdx.x & 31) == 0) sh[rw][wip] = s;
    __syncthreads();
    float mean = (sh[rw][0] + sh[rw][1]) * (1.0f / 256.0f);

    float e0 = h0 - mean, e1 = h1 - mean, e2 = h2 - mean, e3 = h3 - mean;
    float vs = warp_sum(e0 * e0 + e1 * e1 + e2 * e2 + e3 * e3);
    __syncthreads();
    if ((threadIdx.x & 31) == 0) sh[rw][wip] = vs;
    __syncthreads();
    float var = (sh[rw][0] + sh[rw][1]) * (1.0f / 256.0f);
    float rstd = rsqrtf(var + 1e-5f);

    float4 o;
    o.x = 0.5f * (d0 + e0 * rstd * lg.x + lb.x);
    o.y = 0.5f * (d1 + e1 * rstd * lg.y + lb.y);
    o.z = 0.5f * (d2 + e2 * rstd * lg.z + lb.z);
    o.w = 0.5f * (d3 + e3 * rstd * lg.w + lb.w);
    *(float4*)(out + r * 256 + c) = o;
}

// ---------------- launch ----------------
extern "C" void kernel_launch(void* const* d_in, const int* in_sizes, int n_in,
                              void* d_out, int out_size)
{
    const float* inputs  = (const float*)d_in[0];
    const float* adj     = (const float*)d_in[1];
    const float* op_emb  = (const float*)d_in[2];
    const float* dgf_W   = (const float*)d_in[3];
    const float* dgf_b   = (const float*)d_in[4];
    const float* dgf_opW = (const float*)d_in[5];
    const float* dgf_opb = (const float*)d_in[6];
    const float* Wk      = (const float*)d_in[7];
    const float* Wv      = (const float*)d_in[8];
    const float* Wq      = (const float*)d_in[9];
    const float* a_w     = (const float*)d_in[10];
    const float* gat_opW = (const float*)d_in[11];
    const float* gat_opb = (const float*)d_in[12];
    const float* ln_g    = (const float*)d_in[13];
    const float* ln_b    = (const float*)d_in[14];
    float* out = (float*)d_out;

    __half *W3, *Woph, *Xh, *OPh, *Yh, *SUPh, *WhvH, *Gh, *ATTh, *ADJh;
    float *SUP, *S, *AV, *AS;
    cudaGetSymbolAddress((void**)&W3,   g_W3);
    cudaGetSymbolAddress((void**)&Woph, g_Woph);
    cudaGetSymbolAddress((void**)&Xh,   g_Xh);
    cudaGetSymbolAddress((void**)&OPh,  g_OPh);
    cudaGetSymbolAddress((void**)&Yh,   g_Yh);
    cudaGetSymbolAddress((void**)&SUPh, g_SUPh);
    cudaGetSymbolAddress((void**)&WhvH, g_WhvH);
    cudaGetSymbolAddress((void**)&Gh,   g_Gh);
    cudaGetSymbolAddress((void**)&ATTh, g_attnh);
    cudaGetSymbolAddress((void**)&ADJh, g_adjh);
    cudaGetSymbolAddress((void**)&SUP,  g_SUP);
    cudaGetSymbolAddress((void**)&S,    g_S);
    cudaGetSymbolAddress((void**)&AV,   g_AV);
    cudaGetSymbolAddress((void**)&AS,   g_AS);

    const int DSMEM = 2 * STG1 * (int)sizeof(__half) + 256;   // 2 stages, ~74KB
    cudaFuncSetAttribute(gemm_h<0>, cudaFuncAttributeMaxDynamicSharedMemorySize, DSMEM);
    cudaFuncSetAttribute(gemm_h<1>, cudaFuncAttributeMaxDynamicSharedMemorySize, DSMEM);

    const int NOX = 1 << 30;

    // weight prep
    mt_kernel<<<256, 256>>>(Wq, Wk, a_w);
    prep_kernel<<<512, 256>>>(dgf_W, Wv, dgf_opW, gat_opW, dgf_opb, gat_opb);
    // half copies of activations
    f2h_copy<<<(MTOT * DIN / 4 + 255) / 256, 256>>>((const float4*)inputs, (__half2*)Xh, MTOT * DIN / 4);
    f2h_copy<<<(MTOT * DOP / 4 + 255) / 256, 256>>>((const float4*)op_emb, (__half2*)OPh, MTOT * DOP / 4);

    // merged H + gates:
    //   x<6: H = X @ [M|dgf_W|Wv]^T -> Yh | SUP+SUPh | WhvH (mode 3, T=4)
    //   x>=6: gates = OPh @ Woph^T -> Gh (mode 1, T=1, ldch=512)
    {
        dim3 grid(10, MTOT / 128, 1);
        gemm_h<0><<<grid, 128, DSMEM>>>(Xh, W3, SUP, Yh, SUPh, WhvH,
                                        Xh, W3, SUP, NOX,
                                        OPh, Woph, Gh, 6, 64, 64, 1, 1, 512,
                                        256, 256, 256, 256, 4, 3, 0, 0, 0, 0);
    }
    // scores: S[b] = Y[b] @ X[b]^T -> fp32
    {
        dim3 grid(4, 4, BB);
        gemm_h<0><<<grid, 128, DSMEM>>>(Yh, Xh, S, Yh, SUPh, WhvH,
                                        Yh, Xh, S, NOX,
                                        Yh, Xh, Yh, NOX, 0, 0, 0, 0, 0,
                                        256, 256, 512, 0, 4, 0,
                                        (size_t)512 * 256, (size_t)512 * 256, (size_t)512 * 512, 0);
    }
    // leaky + mask + softmax -> attn half; adj -> half
    softmax_kernel<<<MTOT / 2, 256>>>(adj);

    // AV[b] = attn[b] @ Whv[b]  (z<64)   AS[b] = adj[b] @ support[b]  (z>=64)  -> fp32 [512,256]
    {
        dim3 grid(2, 4, 2 * BB);
        gemm_h<1><<<grid, 128, DSMEM>>>(ATTh, WhvH, AV, Yh, SUPh, WhvH,
                                        ADJh, SUPh, AS, BB,
                                        ATTh, WhvH, Yh, NOX, 0, 0, 0, 0, 0,
                                        512, 256, 256, 0, 8, 0,
                                        (size_t)512 * 512, (size_t)512 * 256, (size_t)512 * 256, 0);
    }
    // gates + residual + LN + blend
    final_kernel<<<MTOT / 4, 256>>>(dgf_b, ln_g, ln_b, out);

    (void)in_sizes; (void)n_in; (void)out_size;
}

// round 15
// speedup vs baseline: 1.3562x; 1.0509x over previous
#include <cuda_runtime.h>
#include <cuda_fp16.h>
#include <mma.h>
#include <cstdint>

using namespace nvcuda;

// Problem dims
#define BB    64
#define NN    512
#define DIN   256
#define DOUTD 256
#define DOP   64
#define MTOT  (BB*NN)      // 32768

// ---------------- scratch (static device globals) ----------------
__device__ __half g_W3[768 * 256];                    // rows 0-255: M^T | 256-511: dgf_W^T | 512-767: Wv
__device__ __half g_Woph[512 * 64];                   // rows 0-255: dgf_opW | 256-511: gat_opW
__device__ float  g_biascat[512];
__device__ __half g_Xh[(size_t)MTOT * DIN];           // half inputs
__device__ __half g_OPh[(size_t)MTOT * DOP];          // half op_emb
__device__ __half g_Yh[(size_t)MTOT * 256];           // Y = X @ M (half)
__device__ float  g_SUP[(size_t)MTOT * 256];          // support (exact fp32)
__device__ __half g_SUPh[(size_t)MTOT * 256];         // support (half, for AS GEMM)
__device__ __half g_WhvH[(size_t)MTOT * 256];         // Whv (half, row-major, for AV GEMM)
__device__ __half g_Gh[(size_t)MTOT * 512];           // gate pre-acts (half)
__device__ __half g_Sh[(size_t)BB * NN * NN];         // scores (half)
__device__ __half g_attnh[(size_t)BB * NN * NN];      // softmax(attn) half
__device__ __half g_adjh[(size_t)BB * NN * NN];       // adj half
__device__ float  g_AV[(size_t)MTOT * 256];
__device__ float  g_AS[(size_t)MTOT * 256];

// ---------------- PTX helpers ----------------
__device__ __forceinline__ uint32_t smem_u32(const void* p) {
    uint32_t a;
    asm("{ .reg .u64 t; cvta.to.shared.u64 t, %1; cvt.u32.u64 %0, t; }" : "=r"(a) : "l"(p));
    return a;
}
__device__ __forceinline__ void cp16s(uint32_t dst, const void* src) {
    asm volatile("cp.async.cg.shared.global [%0], [%1], 16;" :: "r"(dst), "l"(src));
}

// ---------------- merged weight prep ----------------
// blocks 0-255: M^T col j = sum_m Wq[m,i]*a_w[m]/16*Wk[m,j]
// blocks 256-767: dgf_W^T | Wv into g_W3 rows 256-767; Woph; biascat
__global__ void prep_all(const float* __restrict__ Wq, const float* __restrict__ Wk,
                         const float* __restrict__ a_w,
                         const float* __restrict__ dgf_W,
                         const float* __restrict__ Wv,
                         const float* __restrict__ dgf_opW,
                         const float* __restrict__ gat_opW,
                         const float* __restrict__ dgf_opb,
                         const float* __restrict__ gat_opb)
{
    if (blockIdx.x < 256) {
        __shared__ float wk[256];
        const int j = blockIdx.x, i = threadIdx.x;
        wk[i] = Wk[i * 256 + j] * a_w[i] * 0.0625f;
        __syncthreads();
        float s = 0.0f;
#pragma unroll 8
        for (int m = 0; m < 256; m++) s += Wq[m * 256 + i] * wk[m];
        g_W3[j * 256 + i] = __float2half_rn(s);
    } else {
        int idx = (blockIdx.x - 256) * blockDim.x + threadIdx.x;   // 0 .. 131071
        {   // g_W3 rows 256-767
            int r = idx >> 8, i = idx & 255;
            float v = (r < 256) ? dgf_W[i * 256 + r]            // rows 256-511: dgf_W^T
                                : Wv[(r - 256) * 256 + i];      // rows 512-767: Wv
            g_W3[(256 + r) * 256 + i] = __float2half_rn(v);
        }
        if (idx < 512 * 64) {
            int n = idx >> 6, p = idx & 63;
            float v = (n < 256) ? dgf_opW[n * 64 + p] : gat_opW[(n - 256) * 64 + p];
            g_Woph[idx] = __float2half_rn(v);
        }
        if (idx < 512) {
            g_biascat[idx] = (idx < 256) ? dgf_opb[idx] : gat_opb[idx - 256];
        }
    }
}

// ---------------- float -> half copy (X and OP merged) ----------------
__global__ void f2h_all(const float4* __restrict__ X, const float4* __restrict__ OP,
                        __half2* __restrict__ Xh, __half2* __restrict__ OPh,
                        int n4x, int n4o)
{
    int i = blockIdx.x * blockDim.x + threadIdx.x;
    const float4* src; __half2* dst; int j;
    if (i < n4x) { src = X; dst = Xh; j = i; }
    else { j = i - n4x; if (j >= n4o) return; src = OP; dst = OPh; }
    float4 v = src[j];
    dst[2 * j]     = __floats2half2_rn(v.x, v.y);
    dst[2 * j + 1] = __floats2half2_rn(v.z, v.w);
}

// ---------------- fp16 wmma GEMM: 128x128 CTA, 4 warps (2x2), 64x64 warp tile ----------------
// 128 threads/CTA, 2 CTAs/SM, BK=64, 2-stage cp.async pipeline.
// BROW=0: C = A @ B^T, B row-major [N,K] (K contiguous)
// BROW=1: C = A @ B,   B row-major [K,N] (N contiguous)
// mode 0: fp32 -> Cf. mode 1: half -> Ch.
// mode 3 (H kernel): col<256 -> Ch(Yh); col<512 -> Cf(SUP,fp32)+Ch2(SUPh,half); else -> Ch3(WhvH,half)
// z-split: blockIdx.z >= zsplit -> (A2,B2,Cf2), z -= zsplit (same shape params).
// x-split: blockIdx.x >= xsplit -> second problem (Ax,Bx,Chx, ldax,ldbx,Tx,modex,ldchx).
constexpr int BKH = 64;
constexpr int LDH = 72;                    // A / BROW0-B smem stride (halfs)
constexpr int LDB_R = 136;                 // BROW1-B smem stride (halfs)
constexpr int ASTG = 128 * LDH;            // 9216 halfs
constexpr int BSTG = 9216;                 // B stage region (BROW0:128*72=9216, BROW1:64*136=8704)
constexpr int STG1 = ASTG + BSTG;          // halfs per stage

template <int BROW>
__global__ __launch_bounds__(128, 2)
void gemm_h(const __half* __restrict__ A, const __half* __restrict__ B,
            float* __restrict__ Cf, __half* __restrict__ Ch,
            __half* __restrict__ Ch2, __half* __restrict__ Ch3,
            const __half* __restrict__ A2, const __half* __restrict__ B2,
            float* __restrict__ Cf2, int zsplit,
            const __half* __restrict__ Ax, const __half* __restrict__ Bx,
            __half* __restrict__ Chx, int xsplit,
            int ldax, int ldbx, int Tx, int modex, int ldchx,
            int lda, int ldb, int ldcf, int ldch, int T, int mode,
            size_t sA, size_t sB, size_t sCf, size_t sCh)
{
    extern __shared__ __half smraw[];
    __half* sm = (__half*)(((uintptr_t)smraw + 127) & ~(uintptr_t)127);

    int z = blockIdx.z;
    if (z >= zsplit) { z -= zsplit; A = A2; B = B2; Cf = Cf2; }
    int bx = blockIdx.x;
    if (bx >= xsplit) {
        bx -= xsplit;
        A = Ax; B = Bx; Ch = Chx;
        lda = ldax; ldb = ldbx; T = Tx; mode = modex; ldch = ldchx;
    }
    A += (size_t)z * sA;
    B += (size_t)z * sB;
    Cf += (size_t)z * sCf;
    Ch += (size_t)z * sCh;

    const int bm = blockIdx.y * 128, bn = bx * 128;
    const int tid = threadIdx.x, warp = tid >> 5;
    const int wm = (warp >> 1) * 64;       // 2 warp rows x 64
    const int wn = (warp & 1) * 64;        // 2 warp cols x 64

    wmma::fragment<wmma::accumulator, 16, 16, 16, float> acc[4][4];
#pragma unroll
    for (int i = 0; i < 4; i++)
#pragma unroll
        for (int j = 0; j < 4; j++) wmma::fill_fragment(acc[i][j], 0.0f);

    auto load_stage = [&](int s, int t) {
        __half* as = sm + (size_t)s * STG1;
        __half* bs = as + ASTG;
        const int k0 = t * BKH;
#pragma unroll
        for (int it = 0; it < 8; it++) {     // A: 128 rows x 64 halfs = 1024 cp16
            int idx = tid + it * 128;
            int rr = idx >> 3, cc = idx & 7;
            cp16s(smem_u32(as + rr * LDH + cc * 8),
                  A + (size_t)(bm + rr) * lda + k0 + cc * 8);
        }
        if (BROW == 0) {
#pragma unroll
            for (int it = 0; it < 8; it++) { // B: 128 N-rows x 64 halfs (K contig)
                int idx = tid + it * 128;
                int rr = idx >> 3, cc = idx & 7;
                cp16s(smem_u32(bs + rr * LDH + cc * 8),
                      B + (size_t)(bn + rr) * ldb + k0 + cc * 8);
            }
        } else {
#pragma unroll
            for (int it = 0; it < 8; it++) { // B: 64 K-rows x 128 halfs (N contig)
                int idx = tid + it * 128;
                int rr = idx >> 4, cc = idx & 15;
                cp16s(smem_u32(bs + rr * LDB_R + cc * 8),
                      B + (size_t)(k0 + rr) * ldb + bn + cc * 8);
            }
        }
        asm volatile("cp.async.commit_group;");
    };

    load_stage(0, 0);

    for (int t = 0; t < T; t++) {
        const int s = t & 1;
        if (t + 1 < T) {
            load_stage(s ^ 1, t + 1);
            asm volatile("cp.async.wait_group 1;");
        } else {
            asm volatile("cp.async.wait_group 0;");
        }
        __syncthreads();

        const __half* as = sm + (size_t)s * STG1;
        const __half* bs = as + ASTG;
#pragma unroll
        for (int kk = 0; kk < BKH; kk += 16) {
            wmma::fragment<wmma::matrix_a, 16, 16, 16, __half, wmma::row_major> af[4];
#pragma unroll
            for (int ii = 0; ii < 4; ii++)
                wmma::load_matrix_sync(af[ii], as + (wm + 16 * ii) * LDH + kk, LDH);
            if (BROW == 0) {
                wmma::fragment<wmma::matrix_b, 16, 16, 16, __half, wmma::col_major> bf[4];
#pragma unroll
                for (int j = 0; j < 4; j++)
                    wmma::load_matrix_sync(bf[j], bs + (wn + 16 * j) * LDH + kk, LDH);
#pragma unroll
                for (int ii = 0; ii < 4; ii++)
#pragma unroll
                    for (int j = 0; j < 4; j++)
                        wmma::mma_sync(acc[ii][j], af[ii], bf[j], acc[ii][j]);
            } else {
                wmma::fragment<wmma::matrix_b, 16, 16, 16, __half, wmma::row_major> bf[4];
#pragma unroll
                for (int j = 0; j < 4; j++)
                    wmma::load_matrix_sync(bf[j], bs + kk * LDB_R + wn + 16 * j, LDB_R);
#pragma unroll
                for (int ii = 0; ii < 4; ii++)
#pragma unroll
                    for (int j = 0; j < 4; j++)
                        wmma::mma_sync(acc[ii][j], af[ii], bf[j], acc[ii][j]);
            }
        }
        __syncthreads();
    }

    // ---- epilogue ----
#pragma unroll
    for (int ii = 0; ii < 4; ii++)
#pragma unroll
        for (int j = 0; j < 4; j++) {
            const int row = bm + wm + 16 * ii;
            const int col = bn + wn + 16 * j;
            if (mode == 0) {
                wmma::store_matrix_sync(Cf + (size_t)row * ldcf + col, acc[ii][j], ldcf,
                                        wmma::mem_row_major);
            } else if (mode == 1) {
                wmma::fragment<wmma::accumulator, 16, 16, 16, __half> hf;
#pragma unroll
                for (int t = 0; t < hf.num_elements; t++)
                    hf.x[t] = __float2half_rn(acc[ii][j].x[t]);
                wmma::store_matrix_sync(Ch + (size_t)row * ldch + col, hf, ldch,
                                        wmma::mem_row_major);
            } else {  // mode 3: H triple output
                if (col < 256) {
                    wmma::fragment<wmma::accumulator, 16, 16, 16, __half> hf;
#pragma unroll
                    for (int t = 0; t < hf.num_elements; t++)
                        hf.x[t] = __float2half_rn(acc[ii][j].x[t]);
                    wmma::store_matrix_sync(Ch + (size_t)row * 256 + col, hf, 256,
                                            wmma::mem_row_major);
                } else if (col < 512) {
                    wmma::store_matrix_sync(Cf + (size_t)row * 256 + (col - 256), acc[ii][j], 256,
                                            wmma::mem_row_major);
                    wmma::fragment<wmma::accumulator, 16, 16, 16, __half> hf;
#pragma unroll
                    for (int t = 0; t < hf.num_elements; t++)
                        hf.x[t] = __float2half_rn(acc[ii][j].x[t]);
                    wmma::store_matrix_sync(Ch2 + (size_t)row * 256 + (col - 256), hf, 256,
                                            wmma::mem_row_major);
                } else {
                    wmma::fragment<wmma::accumulator, 16, 16, 16, __half> hf;
#pragma unroll
                    for (int t = 0; t < hf.num_elements; t++)
                        hf.x[t] = __float2half_rn(acc[ii][j].x[t]);
                    wmma::store_matrix_sync(Ch3 + (size_t)row * 256 + (col - 512), hf, 256,
                                            wmma::mem_row_major);
                }
            }
        }
}

// ---------------- warp reductions ----------------
__device__ __forceinline__ float warp_max(float v) {
#pragma unroll
    for (int o = 16; o; o >>= 1) v = fmaxf(v, __shfl_xor_sync(0xffffffffu, v, o));
    return v;
}
__device__ __forceinline__ float warp_sum(float v) {
#pragma unroll
    for (int o = 16; o; o >>= 1) v += __shfl_xor_sync(0xffffffffu, v, o);
    return v;
}

// ------- leaky+mask+softmax: 4 rows/block, 64 thr/row, 8 cols/thread, half S in/out -------
__global__ void softmax_kernel(const float* __restrict__ adj)
{
    __shared__ float sh[4][2];
    const int rw = threadIdx.x >> 6;                 // row within block (0..3)
    const int t = threadIdx.x & 63;                  // col-thread (8 cols each)
    const int wip = (threadIdx.x >> 5) & 1;          // warp within row
    const size_t r = (size_t)blockIdx.x * 4 + rw;
    const int c = t * 8;

    uint4 us = *(const uint4*)(g_Sh + r * NN + c);
    float4 a0 = *(const float4*)(adj + r * NN + c);
    float4 a1 = *(const float4*)(adj + r * NN + c + 4);

    // adj -> half (16B store)
    {
        __half2 h0 = __floats2half2_rn(a0.x, a0.y);
        __half2 h1 = __floats2half2_rn(a0.z, a0.w);
        __half2 h2 = __floats2half2_rn(a1.x, a1.y);
        __half2 h3 = __floats2half2_rn(a1.z, a1.w);
        uint4 u = make_uint4(*(unsigned*)&h0, *(unsigned*)&h1, *(unsigned*)&h2, *(unsigned*)&h3);
        *(uint4*)(g_adjh + r * NN + c) = u;
    }

    float v[8], aa[8];
    {
        float2 p;
        p = __half22float2(*(__half2*)&us.x); v[0] = p.x; v[1] = p.y;
        p = __half22float2(*(__half2*)&us.y); v[2] = p.x; v[3] = p.y;
        p = __half22float2(*(__half2*)&us.z); v[4] = p.x; v[5] = p.y;
        p = __half22float2(*(__half2*)&us.w); v[6] = p.x; v[7] = p.y;
    }
    aa[0] = a0.x; aa[1] = a0.y; aa[2] = a0.z; aa[3] = a0.w;
    aa[4] = a1.x; aa[5] = a1.y; aa[6] = a1.z; aa[7] = a1.w;

    float m = -1e30f;
#pragma unroll
    for (int i = 0; i < 8; i++) {
        v[i] = (v[i] >= 0.0f ? v[i] : 0.2f * v[i]) * aa[i];
        m = fmaxf(m, v[i]);
    }
    m = warp_max(m);
    if ((threadIdx.x & 31) == 0) sh[rw][wip] = m;
    __syncthreads();
    m = fmaxf(sh[rw][0], sh[rw][1]);

    float e[8], s = 0.0f;
#pragma unroll
    for (int i = 0; i < 8; i++) { e[i] = expf(v[i] - m); s += e[i]; }
    s = warp_sum(s);
    __syncthreads();
    if ((threadIdx.x & 31) == 0) sh[rw][wip] = s;
    __syncthreads();
    s = sh[rw][0] + sh[rw][1];
    float inv = 1.0f / s;

    __half2 o0 = __floats2half2_rn(e[0] * inv, e[1] * inv);
    __half2 o1 = __floats2half2_rn(e[2] * inv, e[3] * inv);
    __half2 o2 = __floats2half2_rn(e[4] * inv, e[5] * inv);
    __half2 o3 = __floats2half2_rn(e[6] * inv, e[7] * inv);
    uint4 u = make_uint4(*(unsigned*)&o0, *(unsigned*)&o1, *(unsigned*)&o2, *(unsigned*)&o3);
    *(uint4*)(g_attnh + r * NN + c) = u;
}

// ---------------- final: 4 rows/block, 64 thr/row, float4 per thread ----------------
__global__ void final_kernel(const float* __restrict__ dgf_b,
                             const float* __restrict__ ln_g,
                             const float* __restrict__ ln_b,
                             float* __restrict__ out)
{
    __shared__ float sh[4][2];
    const int rw = threadIdx.x >> 6;                 // row within block (0..3)
    const int t = threadIdx.x & 63;                  // col-thread (4 cols each)
    const int wip = (threadIdx.x >> 5) & 1;          // warp within row
    const size_t r = (size_t)blockIdx.x * 4 + rw;
    const int c = t * 4;

    float4 sup = *(const float4*)(g_SUP + r * 256 + c);
    float4 as  = *(const float4*)(g_AS + r * 256 + c);
    float4 av  = *(const float4*)(g_AV + r * 256 + c);
    uint2 ug0 = *(const uint2*)(g_Gh + r * 512 + c);
    uint2 ug1 = *(const uint2*)(g_Gh + r * 512 + 256 + c);
    float4 bc0, bc1;
    bc0 = *(const float4*)(g_biascat + c);
    bc1 = *(const float4*)(g_biascat + 256 + c);
    float4 db = *(const float4*)(dgf_b + c);
    float4 lg = *(const float4*)(ln_g + c);
    float4 lb = *(const float4*)(ln_b + c);

    float2 g0a = __half22float2(*(__half2*)&ug0.x);
    float2 g0b = __half22float2(*(__half2*)&ug0.y);
    float2 g1a = __half22float2(*(__half2*)&ug1.x);
    float2 g1b = __half22float2(*(__half2*)&ug1.y);

    float gd0 = 1.0f / (1.0f + expf(-(g0a.x + bc0.x)));
    float gd1 = 1.0f / (1.0f + expf(-(g0a.y + bc0.y)));
    float gd2 = 1.0f / (1.0f + expf(-(g0b.x + bc0.z)));
    float gd3 = 1.0f / (1.0f + expf(-(g0b.y + bc0.w)));
    float gg0 = 1.0f / (1.0f + expf(-(g1a.x + bc1.x)));
    float gg1 = 1.0f / (1.0f + expf(-(g1a.y + bc1.y)));
    float gg2 = 1.0f / (1.0f + expf(-(g1b.x + bc1.z)));
    float gg3 = 1.0f / (1.0f + expf(-(g1b.y + bc1.w)));

    float d0 = gd0 * as.x + sup.x + db.x;
    float d1 = gd1 * as.y + sup.y + db.y;
    float d2 = gd2 * as.z + sup.z + db.z;
    float d3 = gd3 * as.w + sup.w + db.w;

    float h0 = gg0 * av.x, h1 = gg1 * av.y, h2 = gg2 * av.z, h3 = gg3 * av.w;

    float s = warp_sum(h0 + h1 + h2 + h3);
    if ((threadIdx.x & 31) == 0) sh[rw][wip] = s;
    __syncthreads();
    float mean = (sh[rw][0] + sh[rw][1]) * (1.0f / 256.0f);

    float e0 = h0 - mean, e1 = h1 - mean, e2 = h2 - mean, e3 = h3 - mean;
    float vs = warp_sum(e0 * e0 + e1 * e1 + e2 * e2 + e3 * e3);
    __syncthreads();
    if ((threadIdx.x & 31) == 0) sh[rw][wip] = vs;
    __syncthreads();
    float var = (sh[rw][0] + sh[rw][1]) * (1.0f / 256.0f);
    float rstd = rsqrtf(var + 1e-5f);

    float4 o;
    o.x = 0.5f * (d0 + e0 * rstd * lg.x + lb.x);
    o.y = 0.5f * (d1 + e1 * rstd * lg.y + lb.y);
    o.z = 0.5f * (d2 + e2 * rstd * lg.z + lb.z);
    o.w = 0.5f * (d3 + e3 * rstd * lg.w + lb.w);
    *(float4*)(out + r * 256 + c) = o;
}

// ---------------- launch ----------------
extern "C" void kernel_launch(void* const* d_in, const int* in_sizes, int n_in,
                              void* d_out, int out_size)
{
    const float* inputs  = (const float*)d_in[0];
    const float* adj     = (const float*)d_in[1];
    const float* op_emb  = (const float*)d_in[2];
    const float* dgf_W   = (const float*)d_in[3];
    const float* dgf_b   = (const float*)d_in[4];
    const float* dgf_opW = (const float*)d_in[5];
    const float* dgf_opb = (const float*)d_in[6];
    const float* Wk      = (const float*)d_in[7];
    const float* Wv      = (const float*)d_in[8];
    const float* Wq      = (const float*)d_in[9];
    const float* a_w     = (const float*)d_in[10];
    const float* gat_opW = (const float*)d_in[11];
    const float* gat_opb = (const float*)d_in[12];
    const float* ln_g    = (const float*)d_in[13];
    const float* ln_b    = (const float*)d_in[14];
    float* out = (float*)d_out;

    __half *W3, *Woph, *Xh, *OPh, *Yh, *SUPh, *WhvH, *Gh, *Sh, *ATTh, *ADJh;
    float *SUP, *AV, *AS;
    cudaGetSymbolAddress((void**)&W3,   g_W3);
    cudaGetSymbolAddress((void**)&Woph, g_Woph);
    cudaGetSymbolAddress((void**)&Xh,   g_Xh);
    cudaGetSymbolAddress((void**)&OPh,  g_OPh);
    cudaGetSymbolAddress((void**)&Yh,   g_Yh);
    cudaGetSymbolAddress((void**)&SUPh, g_SUPh);
    cudaGetSymbolAddress((void**)&WhvH, g_WhvH);
    cudaGetSymbolAddress((void**)&Gh,   g_Gh);
    cudaGetSymbolAddress((void**)&Sh,   g_Sh);
    cudaGetSymbolAddress((void**)&ATTh, g_attnh);
    cudaGetSymbolAddress((void**)&ADJh, g_adjh);
    cudaGetSymbolAddress((void**)&SUP,  g_SUP);
    cudaGetSymbolAddress((void**)&AV,   g_AV);
    cudaGetSymbolAddress((void**)&AS,   g_AS);

    const int DSMEM = 2 * STG1 * (int)sizeof(__half) + 256;   // 2 stages, ~74KB
    cudaFuncSetAttribute(gemm_h<0>, cudaFuncAttributeMaxDynamicSharedMemorySize, DSMEM);
    cudaFuncSetAttribute(gemm_h<1>, cudaFuncAttributeMaxDynamicSharedMemorySize, DSMEM);

    const int NOX = 1 << 30;

    // merged weight prep (mt + pack)
    prep_all<<<768, 256>>>(Wq, Wk, a_w, dgf_W, Wv, dgf_opW, gat_opW, dgf_opb, gat_opb);
    // merged half copies of activations
    {
        int n4x = MTOT * DIN / 4, n4o = MTOT * DOP / 4;
        f2h_all<<<(n4x + n4o + 255) / 256, 256>>>((const float4*)inputs, (const float4*)op_emb,
                                                  (__half2*)Xh, (__half2*)OPh, n4x, n4o);
    }

    // merged H + gates:
    //   x<6: H = X @ [M|dgf_W|Wv]^T -> Yh | SUP+SUPh | WhvH (mode 3, T=4)
    //   x>=6: gates = OPh @ Woph^T -> Gh (mode 1, T=1, ldch=512)
    {
        dim3 grid(10, MTOT / 128, 1);
        gemm_h<0><<<grid, 128, DSMEM>>>(Xh, W3, SUP, Yh, SUPh, WhvH,
                                        Xh, W3, SUP, NOX,
                                        OPh, Woph, Gh, 6, 64, 64, 1, 1, 512,
                                        256, 256, 256, 256, 4, 3, 0, 0, 0, 0);
    }
    // scores: Sh[b] = Y[b] @ X[b]^T -> half
    {
        dim3 grid(4, 4, BB);
        gemm_h<0><<<grid, 128, DSMEM>>>(Yh, Xh, SUP, Sh, SUPh, WhvH,
                                        Yh, Xh, SUP, NOX,
                                        Yh, Xh, Sh, NOX, 0, 0, 0, 0, 0,
                                        256, 256, 0, 512, 4, 1,
                                        (size_t)512 * 256, (size_t)512 * 256, 0, (size_t)512 * 512);
    }
    // leaky + mask + softmax -> attn half; adj -> half
    softmax_kernel<<<MTOT / 4, 256>>>(adj);

    // AV[b] = attn[b] @ Whv[b]  (z<64)   AS[b] = adj[b] @ support[b]  (z>=64)  -> fp32 [512,256]
    {
        dim3 grid(2, 4, 2 * BB);
        gemm_h<1><<<grid, 128, DSMEM>>>(ATTh, WhvH, AV, Yh, SUPh, WhvH,
                                        ADJh, SUPh, AS, BB,
                                        ATTh, WhvH, Yh, NOX, 0, 0, 0, 0, 0,
                                        512, 256, 256, 0, 8, 0,
                                        (size_t)512 * 512, (size_t)512 * 256, (size_t)512 * 256, 0);
    }
    // gates + residual + LN + blend
    final_kernel<<<MTOT / 4, 256>>>(dgf_b, ln_g, ln_b, out);

    (void)in_sizes; (void)n_in; (void)out_size;
}

// round 16
// speedup vs baseline: 1.3997x; 1.0320x over previous
#include <cuda_runtime.h>
#include <cuda_fp16.h>
#include <mma.h>
#include <cstdint>

using namespace nvcuda;

// Problem dims
#define BB    64
#define NN    512
#define DIN   256
#define DOUTD 256
#define DOP   64
#define MTOT  (BB*NN)      // 32768

// ---------------- scratch (static device globals) ----------------
__device__ __half g_W3[768 * 256];                    // rows 0-255: M^T | 256-511: dgf_W^T | 512-767: Wv
__device__ __half g_Woph[512 * 64];                   // rows 0-255: dgf_opW | 256-511: gat_opW
__device__ float  g_biascat[512];
__device__ __half g_Xh[(size_t)MTOT * DIN];           // half inputs
__device__ __half g_OPh[(size_t)MTOT * DOP];          // half op_emb
__device__ __half g_Yh[(size_t)MTOT * 256];           // Y = X @ M (half)
__device__ __half g_SUPh[(size_t)MTOT * 256];         // support (half)
__device__ __half g_WhvH[(size_t)MTOT * 256];         // Whv (half, row-major)
__device__ __half g_Gh[(size_t)MTOT * 512];           // gate pre-acts (half)
__device__ __half g_Sh[(size_t)BB * NN * NN];         // scores (half)
__device__ __half g_attnh[(size_t)BB * NN * NN];      // softmax(attn) half
__device__ __half g_adjh[(size_t)BB * NN * NN];       // adj half
__device__ __half g_AVh[(size_t)MTOT * 256];          // attn @ Whv (half)
__device__ __half g_ASh[(size_t)MTOT * 256];          // adj @ support (half)

// ---------------- PTX helpers ----------------
__device__ __forceinline__ uint32_t smem_u32(const void* p) {
    uint32_t a;
    asm("{ .reg .u64 t; cvta.to.shared.u64 t, %1; cvt.u32.u64 %0, t; }" : "=r"(a) : "l"(p));
    return a;
}
__device__ __forceinline__ void cp16s(uint32_t dst, const void* src) {
    asm volatile("cp.async.cg.shared.global [%0], [%1], 16;" :: "r"(dst), "l"(src));
}

// ---------------- merged weight prep ----------------
__global__ void prep_all(const float* __restrict__ Wq, const float* __restrict__ Wk,
                         const float* __restrict__ a_w,
                         const float* __restrict__ dgf_W,
                         const float* __restrict__ Wv,
                         const float* __restrict__ dgf_opW,
                         const float* __restrict__ gat_opW,
                         const float* __restrict__ dgf_opb,
                         const float* __restrict__ gat_opb)
{
    if (blockIdx.x < 256) {
        __shared__ float wk[256];
        const int j = blockIdx.x, i = threadIdx.x;
        wk[i] = Wk[i * 256 + j] * a_w[i] * 0.0625f;
        __syncthreads();
        float s = 0.0f;
#pragma unroll 8
        for (int m = 0; m < 256; m++) s += Wq[m * 256 + i] * wk[m];
        g_W3[j * 256 + i] = __float2half_rn(s);
    } else {
        int idx = (blockIdx.x - 256) * blockDim.x + threadIdx.x;   // 0 .. 131071
        {   // g_W3 rows 256-767
            int r = idx >> 8, i = idx & 255;
            float v = (r < 256) ? dgf_W[i * 256 + r]            // rows 256-511: dgf_W^T
                                : Wv[(r - 256) * 256 + i];      // rows 512-767: Wv
            g_W3[(256 + r) * 256 + i] = __float2half_rn(v);
        }
        if (idx < 512 * 64) {
            int n = idx >> 6, p = idx & 63;
            float v = (n < 256) ? dgf_opW[n * 64 + p] : gat_opW[(n - 256) * 64 + p];
            g_Woph[idx] = __float2half_rn(v);
        }
        if (idx < 512) {
            g_biascat[idx] = (idx < 256) ? dgf_opb[idx] : gat_opb[idx - 256];
        }
    }
}

// ---------------- float -> half copy (X, OP, adj merged) ----------------
__global__ void f2h_all(const float4* __restrict__ X, const float4* __restrict__ OP,
                        const float4* __restrict__ AJ,
                        __half2* __restrict__ Xh, __half2* __restrict__ OPh,
                        __half2* __restrict__ AJh,
                        int n4x, int n4o, int n4a)
{
    int i = blockIdx.x * blockDim.x + threadIdx.x;
    const float4* src; __half2* dst; int j;
    if (i < n4x) { src = X; dst = Xh; j = i; }
    else if ((j = i - n4x) < n4o) { src = OP; dst = OPh; }
    else { j -= n4o; if (j >= n4a) return; src = AJ; dst = AJh; }
    float4 v = src[j];
    dst[2 * j]     = __floats2half2_rn(v.x, v.y);
    dst[2 * j + 1] = __floats2half2_rn(v.z, v.w);
}

// ---------------- fp16 wmma GEMM: 128x128 CTA, 4 warps (2x2), 64x64 warp tile ----------------
// 128 threads/CTA, 2 CTAs/SM, BK=64, 2-stage cp.async pipeline. All outputs half.
// BROW=0: C = A @ B^T, B row-major [N,K] (K contiguous)
// BROW=1: C = A @ B,   B row-major [K,N] (N contiguous)
// mode 1: half -> Ch. mode 3 (H kernel): col<256 -> Ch(Yh); col<512 -> Ch2(SUPh); else -> Ch3(WhvH)
// z-split: blockIdx.z >= zsplit -> (A2,B2,Chz), z -= zsplit (same shape params).
// x-split: blockIdx.x >= xsplit -> second problem (Ax,Bx,Chx, ldax,ldbx,Tx,modex,ldchx).
constexpr int BKH = 64;
constexpr int LDH = 72;                    // A / BROW0-B smem stride (halfs)
constexpr int LDB_R = 136;                 // BROW1-B smem stride (halfs)
constexpr int ASTG = 128 * LDH;            // 9216 halfs
constexpr int BSTG = 9216;                 // B stage region
constexpr int STG1 = ASTG + BSTG;          // halfs per stage

template <int BROW>
__global__ __launch_bounds__(128, 2)
void gemm_h(const __half* __restrict__ A, const __half* __restrict__ B,
            __half* __restrict__ Ch, __half* __restrict__ Ch2, __half* __restrict__ Ch3,
            const __half* __restrict__ A2, const __half* __restrict__ B2,
            __half* __restrict__ Chz, int zsplit,
            const __half* __restrict__ Ax, const __half* __restrict__ Bx,
            __half* __restrict__ Chx, int xsplit,
            int ldax, int ldbx, int Tx, int modex, int ldchx,
            int lda, int ldb, int ldch, int T, int mode,
            size_t sA, size_t sB, size_t sCh)
{
    extern __shared__ __half smraw[];
    __half* sm = (__half*)(((uintptr_t)smraw + 127) & ~(uintptr_t)127);

    int z = blockIdx.z;
    if (z >= zsplit) { z -= zsplit; A = A2; B = B2; Ch = Chz; }
    int bx = blockIdx.x;
    if (bx >= xsplit) {
        bx -= xsplit;
        A = Ax; B = Bx; Ch = Chx;
        lda = ldax; ldb = ldbx; T = Tx; mode = modex; ldch = ldchx;
    }
    A += (size_t)z * sA;
    B += (size_t)z * sB;
    Ch += (size_t)z * sCh;

    const int bm = blockIdx.y * 128, bn = bx * 128;
    const int tid = threadIdx.x, warp = tid >> 5;
    const int wm = (warp >> 1) * 64;       // 2 warp rows x 64
    const int wn = (warp & 1) * 64;        // 2 warp cols x 64

    wmma::fragment<wmma::accumulator, 16, 16, 16, float> acc[4][4];
#pragma unroll
    for (int i = 0; i < 4; i++)
#pragma unroll
        for (int j = 0; j < 4; j++) wmma::fill_fragment(acc[i][j], 0.0f);

    auto load_stage = [&](int s, int t) {
        __half* as = sm + (size_t)s * STG1;
        __half* bs = as + ASTG;
        const int k0 = t * BKH;
#pragma unroll
        for (int it = 0; it < 8; it++) {     // A: 128 rows x 64 halfs = 1024 cp16
            int idx = tid + it * 128;
            int rr = idx >> 3, cc = idx & 7;
            cp16s(smem_u32(as + rr * LDH + cc * 8),
                  A + (size_t)(bm + rr) * lda + k0 + cc * 8);
        }
        if (BROW == 0) {
#pragma unroll
            for (int it = 0; it < 8; it++) { // B: 128 N-rows x 64 halfs (K contig)
                int idx = tid + it * 128;
                int rr = idx >> 3, cc = idx & 7;
                cp16s(smem_u32(bs + rr * LDH + cc * 8),
                      B + (size_t)(bn + rr) * ldb + k0 + cc * 8);
            }
        } else {
#pragma unroll
            for (int it = 0; it < 8; it++) { // B: 64 K-rows x 128 halfs (N contig)
                int idx = tid + it * 128;
                int rr = idx >> 4, cc = idx & 15;
                cp16s(smem_u32(bs + rr * LDB_R + cc * 8),
                      B + (size_t)(k0 + rr) * ldb + bn + cc * 8);
            }
        }
        asm volatile("cp.async.commit_group;");
    };

    load_stage(0, 0);

    for (int t = 0; t < T; t++) {
        const int s = t & 1;
        if (t + 1 < T) {
            load_stage(s ^ 1, t + 1);
            asm volatile("cp.async.wait_group 1;");
        } else {
            asm volatile("cp.async.wait_group 0;");
        }
        __syncthreads();

        const __half* as = sm + (size_t)s * STG1;
        const __half* bs = as + ASTG;
#pragma unroll
        for (int kk = 0; kk < BKH; kk += 16) {
            wmma::fragment<wmma::matrix_a, 16, 16, 16, __half, wmma::row_major> af[4];
#pragma unroll
            for (int ii = 0; ii < 4; ii++)
                wmma::load_matrix_sync(af[ii], as + (wm + 16 * ii) * LDH + kk, LDH);
            if (BROW == 0) {
                wmma::fragment<wmma::matrix_b, 16, 16, 16, __half, wmma::col_major> bf[4];
#pragma unroll
                for (int j = 0; j < 4; j++)
                    wmma::load_matrix_sync(bf[j], bs + (wn + 16 * j) * LDH + kk, LDH);
#pragma unroll
                for (int ii = 0; ii < 4; ii++)
#pragma unroll
                    for (int j = 0; j < 4; j++)
                        wmma::mma_sync(acc[ii][j], af[ii], bf[j], acc[ii][j]);
            } else {
                wmma::fragment<wmma::matrix_b, 16, 16, 16, __half, wmma::row_major> bf[4];
#pragma unroll
                for (int j = 0; j < 4; j++)
                    wmma::load_matrix_sync(bf[j], bs + kk * LDB_R + wn + 16 * j, LDB_R);
#pragma unroll
                for (int ii = 0; ii < 4; ii++)
#pragma unroll
                    for (int j = 0; j < 4; j++)
                        wmma::mma_sync(acc[ii][j], af[ii], bf[j], acc[ii][j]);
            }
        }
        __syncthreads();
    }

    // ---- epilogue (all half) ----
#pragma unroll
    for (int ii = 0; ii < 4; ii++)
#pragma unroll
        for (int j = 0; j < 4; j++) {
            const int row = bm + wm + 16 * ii;
            const int col = bn + wn + 16 * j;
            wmma::fragment<wmma::accumulator, 16, 16, 16, __half> hf;
#pragma unroll
            for (int t = 0; t < hf.num_elements; t++)
                hf.x[t] = __float2half_rn(acc[ii][j].x[t]);
            if (mode == 1) {
                wmma::store_matrix_sync(Ch + (size_t)row * ldch + col, hf, ldch,
                                        wmma::mem_row_major);
            } else {  // mode 3: triple half output
                if (col < 256)
                    wmma::store_matrix_sync(Ch + (size_t)row * 256 + col, hf, 256,
                                            wmma::mem_row_major);
                else if (col < 512)
                    wmma::store_matrix_sync(Ch2 + (size_t)row * 256 + (col - 256), hf, 256,
                                            wmma::mem_row_major);
                else
                    wmma::store_matrix_sync(Ch3 + (size_t)row * 256 + (col - 512), hf, 256,
                                            wmma::mem_row_major);
            }
        }
}

// ---------------- warp reductions ----------------
__device__ __forceinline__ float warp_max(float v) {
#pragma unroll
    for (int o = 16; o; o >>= 1) v = fmaxf(v, __shfl_xor_sync(0xffffffffu, v, o));
    return v;
}
__device__ __forceinline__ float warp_sum(float v) {
#pragma unroll
    for (int o = 16; o; o >>= 1) v += __shfl_xor_sync(0xffffffffu, v, o);
    return v;
}

// ------- leaky+mask+softmax: 4 rows/block, 64 thr/row, 8 cols/thread, all-half I/O -------
__global__ void softmax_kernel()
{
    __shared__ float sh[4][2];
    const int rw = threadIdx.x >> 6;                 // row within block (0..3)
    const int t = threadIdx.x & 63;                  // col-thread (8 cols each)
    const int wip = (threadIdx.x >> 5) & 1;          // warp within row
    const size_t r = (size_t)blockIdx.x * 4 + rw;
    const int c = t * 8;

    uint4 us = *(const uint4*)(g_Sh + r * NN + c);
    uint4 ua = *(const uint4*)(g_adjh + r * NN + c);

    float v[8], aa[8];
    {
        float2 p;
        p = __half22float2(*(__half2*)&us.x); v[0] = p.x; v[1] = p.y;
        p = __half22float2(*(__half2*)&us.y); v[2] = p.x; v[3] = p.y;
        p = __half22float2(*(__half2*)&us.z); v[4] = p.x; v[5] = p.y;
        p = __half22float2(*(__half2*)&us.w); v[6] = p.x; v[7] = p.y;
        p = __half22float2(*(__half2*)&ua.x); aa[0] = p.x; aa[1] = p.y;
        p = __half22float2(*(__half2*)&ua.y); aa[2] = p.x; aa[3] = p.y;
        p = __half22float2(*(__half2*)&ua.z); aa[4] = p.x; aa[5] = p.y;
        p = __half22float2(*(__half2*)&ua.w); aa[6] = p.x; aa[7] = p.y;
    }

    float m = -1e30f;
#pragma unroll
    for (int i = 0; i < 8; i++) {
        v[i] = (v[i] >= 0.0f ? v[i] : 0.2f * v[i]) * aa[i];
        m = fmaxf(m, v[i]);
    }
    m = warp_max(m);
    if ((threadIdx.x & 31) == 0) sh[rw][wip] = m;
    __syncthreads();
    m = fmaxf(sh[rw][0], sh[rw][1]);

    float e[8], s = 0.0f;
#pragma unroll
    for (int i = 0; i < 8; i++) { e[i] = expf(v[i] - m); s += e[i]; }
    s = warp_sum(s);
    __syncthreads();
    if ((threadIdx.x & 31) == 0) sh[rw][wip] = s;
    __syncthreads();
    s = sh[rw][0] + sh[rw][1];
    float inv = 1.0f / s;

    __half2 o0 = __floats2half2_rn(e[0] * inv, e[1] * inv);
    __half2 o1 = __floats2half2_rn(e[2] * inv, e[3] * inv);
    __half2 o2 = __floats2half2_rn(e[4] * inv, e[5] * inv);
    __half2 o3 = __floats2half2_rn(e[6] * inv, e[7] * inv);
    uint4 u = make_uint4(*(unsigned*)&o0, *(unsigned*)&o1, *(unsigned*)&o2, *(unsigned*)&o3);
    *(uint4*)(g_attnh + r * NN + c) = u;
}

// ---------------- final: 4 rows/block, 64 thr/row, 4 cols/thread, half inputs ----------------
__global__ void final_kernel(const float* __restrict__ dgf_b,
                             const float* __restrict__ ln_g,
                             const float* __restrict__ ln_b,
                             float* __restrict__ out)
{
    __shared__ float sh[4][2];
    const int rw = threadIdx.x >> 6;                 // row within block (0..3)
    const int t = threadIdx.x & 63;                  // col-thread (4 cols each)
    const int wip = (threadIdx.x >> 5) & 1;          // warp within row
    const size_t r = (size_t)blockIdx.x * 4 + rw;
    const int c = t * 4;

    uint2 usup = *(const uint2*)(g_SUPh + r * 256 + c);
    uint2 uas  = *(const uint2*)(g_ASh + r * 256 + c);
    uint2 uav  = *(const uint2*)(g_AVh + r * 256 + c);
    uint2 ug0 = *(const uint2*)(g_Gh + r * 512 + c);
    uint2 ug1 = *(const uint2*)(g_Gh + r * 512 + 256 + c);
    float4 bc0 = *(const float4*)(g_biascat + c);
    float4 bc1 = *(const float4*)(g_biascat + 256 + c);
    float4 db = *(const float4*)(dgf_b + c);
    float4 lg = *(const float4*)(ln_g + c);
    float4 lb = *(const float4*)(ln_b + c);

    float2 sa = __half22float2(*(__half2*)&usup.x);
    float2 sb = __half22float2(*(__half2*)&usup.y);
    float2 aa = __half22float2(*(__half2*)&uas.x);
    float2 ab = __half22float2(*(__half2*)&uas.y);
    float2 va = __half22float2(*(__half2*)&uav.x);
    float2 vb = __half22float2(*(__half2*)&uav.y);
    float2 g0a = __half22float2(*(__half2*)&ug0.x);
    float2 g0b = __half22float2(*(__half2*)&ug0.y);
    float2 g1a = __half22float2(*(__half2*)&ug1.x);
    float2 g1b = __half22float2(*(__half2*)&ug1.y);

    float gd0 = 1.0f / (1.0f + expf(-(g0a.x + bc0.x)));
    float gd1 = 1.0f / (1.0f + expf(-(g0a.y + bc0.y)));
    float gd2 = 1.0f / (1.0f + expf(-(g0b.x + bc0.z)));
    float gd3 = 1.0f / (1.0f + expf(-(g0b.y + bc0.w)));
    float gg0 = 1.0f / (1.0f + expf(-(g1a.x + bc1.x)));
    float gg1 = 1.0f / (1.0f + expf(-(g1a.y + bc1.y)));
    float gg2 = 1.0f / (1.0f + expf(-(g1b.x + bc1.z)));
    float gg3 = 1.0f / (1.0f + expf(-(g1b.y + bc1.w)));

    float d0 = gd0 * aa.x + sa.x + db.x;
    float d1 = gd1 * aa.y + sa.y + db.y;
    float d2 = gd2 * ab.x + sb.x + db.z;
    float d3 = gd3 * ab.y + sb.y + db.w;

    float h0 = gg0 * va.x, h1 = gg1 * va.y, h2 = gg2 * vb.x, h3 = gg3 * vb.y;

    float s = warp_sum(h0 + h1 + h2 + h3);
    if ((threadIdx.x & 31) == 0) sh[rw][wip] = s;
    __syncthreads();
    float mean = (sh[rw][0] + sh[rw][1]) * (1.0f / 256.0f);

    float e0 = h0 - mean, e1 = h1 - mean, e2 = h2 - mean, e3 = h3 - mean;
    float vs = warp_sum(e0 * e0 + e1 * e1 + e2 * e2 + e3 * e3);
    __syncthreads();
    if ((threadIdx.x & 31) == 0) sh[rw][wip] = vs;
    __syncthreads();
    float var = (sh[rw][0] + sh[rw][1]) * (1.0f / 256.0f);
    float rstd = rsqrtf(var + 1e-5f);

    float4 o;
    o.x = 0.5f * (d0 + e0 * rstd * lg.x + lb.x);
    o.y = 0.5f * (d1 + e1 * rstd * lg.y + lb.y);
    o.z = 0.5f * (d2 + e2 * rstd * lg.z + lb.z);
    o.w = 0.5f * (d3 + e3 * rstd * lg.w + lb.w);
    *(float4*)(out + r * 256 + c) = o;
}

// ---------------- launch ----------------
extern "C" void kernel_launch(void* const* d_in, const int* in_sizes, int n_in,
                              void* d_out, int out_size)
{
    const float* inputs  = (const float*)d_in[0];
    const float* adj     = (const float*)d_in[1];
    const float* op_emb  = (const float*)d_in[2];
    const float* dgf_W   = (const float*)d_in[3];
    const float* dgf_b   = (const float*)d_in[4];
    const float* dgf_opW = (const float*)d_in[5];
    const float* dgf_opb = (const float*)d_in[6];
    const float* Wk      = (const float*)d_in[7];
    const float* Wv      = (const float*)d_in[8];
    const float* Wq      = (const float*)d_in[9];
    const float* a_w     = (const float*)d_in[10];
    const float* gat_opW = (const float*)d_in[11];
    const float* gat_opb = (const float*)d_in[12];
    const float* ln_g    = (const float*)d_in[13];
    const float* ln_b    = (const float*)d_in[14];
    float* out = (float*)d_out;

    __half *W3, *Woph, *Xh, *OPh, *Yh, *SUPh, *WhvH, *Gh, *Sh, *ATTh, *ADJh, *AVh, *ASh;
    cudaGetSymbolAddress((void**)&W3,   g_W3);
    cudaGetSymbolAddress((void**)&Woph, g_Woph);
    cudaGetSymbolAddress((void**)&Xh,   g_Xh);
    cudaGetSymbolAddress((void**)&OPh,  g_OPh);
    cudaGetSymbolAddress((void**)&Yh,   g_Yh);
    cudaGetSymbolAddress((void**)&SUPh, g_SUPh);
    cudaGetSymbolAddress((void**)&WhvH, g_WhvH);
    cudaGetSymbolAddress((void**)&Gh,   g_Gh);
    cudaGetSymbolAddress((void**)&Sh,   g_Sh);
    cudaGetSymbolAddress((void**)&ATTh, g_attnh);
    cudaGetSymbolAddress((void**)&ADJh, g_adjh);
    cudaGetSymbolAddress((void**)&AVh,  g_AVh);
    cudaGetSymbolAddress((void**)&ASh,  g_ASh);

    const int DSMEM = 2 * STG1 * (int)sizeof(__half) + 256;   // 2 stages, ~74KB
    cudaFuncSetAttribute(gemm_h<0>, cudaFuncAttributeMaxDynamicSharedMemorySize, DSMEM);
    cudaFuncSetAttribute(gemm_h<1>, cudaFuncAttributeMaxDynamicSharedMemorySize, DSMEM);

    const int NOX = 1 << 30;

    // merged weight prep
    prep_all<<<768, 256>>>(Wq, Wk, a_w, dgf_W, Wv, dgf_opW, gat_opW, dgf_opb, gat_opb);
    // merged half copies: X, op_emb, adj
    {
        int n4x = MTOT * DIN / 4, n4o = MTOT * DOP / 4, n4a = BB * NN * NN / 4;
        f2h_all<<<(n4x + n4o + n4a + 255) / 256, 256>>>(
            (const float4*)inputs, (const float4*)op_emb, (const float4*)adj,
            (__half2*)Xh, (__half2*)OPh, (__half2*)ADJh, n4x, n4o, n4a);
    }

    // merged H + gates:
    //   x<6: H = X @ [M|dgf_W|Wv]^T -> Yh | SUPh | WhvH (mode 3, T=4)
    //   x>=6: gates = OPh @ Woph^T -> Gh (mode 1, T=1, ldch=512)
    {
        dim3 grid(10, MTOT / 128, 1);
        gemm_h<0><<<grid, 128, DSMEM>>>(Xh, W3, Yh, SUPh, WhvH,
                                        Xh, W3, Yh, NOX,
                                        OPh, Woph, Gh, 6, 64, 64, 1, 1, 512,
                                        256, 256, 256, 4, 3, 0, 0, 0);
    }
    // scores: Sh[b] = Y[b] @ X[b]^T -> half
    {
        dim3 grid(4, 4, BB);
        gemm_h<0><<<grid, 128, DSMEM>>>(Yh, Xh, Sh, SUPh, WhvH,
                                        Yh, Xh, Sh, NOX,
                                        Yh, Xh, Sh, NOX, 0, 0, 0, 0, 0,
                                        256, 256, 512, 4, 1,
                                        (size_t)512 * 256, (size_t)512 * 256, (size_t)512 * 512);
    }
    // leaky + mask + softmax -> attn half (reads Sh + adjh)
    softmax_kernel<<<MTOT / 4, 256>>>();

    // AV[b] = attn[b] @ Whv[b]  (z<64)   AS[b] = adjh[b] @ SUPh[b]  (z>=64)  -> half [512,256]
    {
        dim3 grid(2, 4, 2 * BB);
        gemm_h<1><<<grid, 128, DSMEM>>>(ATTh, WhvH, AVh, SUPh, WhvH,
                                        ADJh, SUPh, ASh, BB,
                                        ATTh, WhvH, AVh, NOX, 0, 0, 0, 0, 0,
                                        512, 256, 256, 8, 1,
                                        (size_t)512 * 512, (size_t)512 * 256, (size_t)512 * 256);
    }
    // gates + residual + LN + blend
    final_kernel<<<MTOT / 4, 256>>>(dgf_b, ln_g, ln_b, out);

    (void)in_sizes; (void)n_in; (void)out_size;
}